// round 3
// baseline (speedup 1.0000x reference)
#include <cuda_runtime.h>

#define BB 4
#define NN 160
#define DD 64
#define ZIc 64
#define ZEc 64
#define LL 4
#define LEc 8
#define H1 128
#define H2 64
#define NP 164   // padded pjT row stride

// Scratch (allocation-free: __device__ globals)
__device__ float g_piA[BB * NN * H1];
__device__ float g_pjA[BB * NN * H1];
__device__ float g_qiA[BB * NN * H1];
__device__ float g_qjA[BB * NN * H1];
__device__ float g_qlA[LL * H1];
__device__ float g_W2dup_i[H1 * H2 * 2];  // (w,w) pairs
__device__ float g_W2dup_l[H1 * H2 * 2];

// ---------------------------------------------------------------------------
// Kernel 0: duplicate W2 entries into (w,w) pairs for j-packed f32x2 FMAs
// ---------------------------------------------------------------------------
__global__ void dup_kernel(const float* __restrict__ Wi2,
                           const float* __restrict__ Wl2)
{
    const int idx = blockIdx.x * blockDim.x + threadIdx.x;  // 0..8191
    const float a = Wi2[idx];
    const float b = Wl2[idx];
    g_W2dup_i[2 * idx]     = a;
    g_W2dup_i[2 * idx + 1] = a;
    g_W2dup_l[2 * idx]     = b;
    g_W2dup_l[2 * idx + 1] = b;
}

// ---------------------------------------------------------------------------
// Kernel 1: per-(b,n) projections (tiny)
// ---------------------------------------------------------------------------
__global__ void proj_kernel(const float* __restrict__ ne,
                            const float* __restrict__ zi,
                            const float* __restrict__ ze,
                            const float* __restrict__ lag,
                            const float* __restrict__ Wi1,
                            const float* __restrict__ bi1,
                            const float* __restrict__ Wl1,
                            const float* __restrict__ bl1)
{
    __shared__ float s_ne[DD], s_zi[ZIc], s_ze[ZEc];
    const int bid = blockIdx.x;
    const int b   = bid / NN;
    const int k   = threadIdx.x;

    if (k < DD)  s_ne[k] = ne[bid * DD + k];
    if (k < ZIc) s_zi[k] = zi[b * ZIc + k];
    if (k < ZEc) s_ze[k] = ze[b * ZEc + k];
    __syncthreads();

    float api = bi1[k];
    float apj = 0.f;
    float aqi = bl1[k];
    float aqj = 0.f;

    #pragma unroll 8
    for (int d = 0; d < DD; d++) {
        const float nd = s_ne[d];
        api += nd * Wi1[d * H1 + k];
        apj += nd * Wi1[(DD + d) * H1 + k];
        aqi += nd * Wl1[d * H1 + k];
        aqj += nd * Wl1[(DD + d) * H1 + k];
    }
    #pragma unroll 8
    for (int z = 0; z < ZIc; z++) {
        api += s_zi[z] * Wi1[(2 * DD + z) * H1 + k];
        aqi += s_ze[z] * Wl1[(2 * DD + z) * H1 + k];
    }

    g_piA[bid * H1 + k] = api;
    g_pjA[bid * H1 + k] = apj;
    g_qiA[bid * H1 + k] = aqi;
    g_qjA[bid * H1 + k] = aqj;

    if (bid == 0) {
        #pragma unroll
        for (int l = 0; l < LL; l++) {
            float a = 0.f;
            #pragma unroll
            for (int e = 0; e < LEc; e++)
                a += lag[l * LEc + e] * Wl1[(2 * DD + ZEc + e) * H1 + k];
            g_qlA[l * H1 + k] = a;
        }
    }
}

// ---------------------------------------------------------------------------
// Kernel 2: pairwise MLP. Per block: one (b,[l]), 4 i's sequentially.
// Phase A (per i): s_h[k][j] = relu(u_i[k] + pjT[k][j])    (320 thr coop)
// Phase B (per i): GEMM s_h(128xk,160j) x W2(128,64) j-packed f32x2,
//                  tile 8j x 4m per thread, 320 threads = 20jt x 16mt.
// ---------------------------------------------------------------------------
extern __shared__ float smem[];

__global__ __launch_bounds__(320, 1) void pair_kernel(
    const float* __restrict__ bi2, const float* __restrict__ Wi3,
    const float* __restrict__ bi3,
    const float* __restrict__ bl2, const float* __restrict__ Wl3,
    const float* __restrict__ bl3,
    float* __restrict__ out)
{
    float* s_pjT = smem;                  // H1 * NP
    float* s_h   = s_pjT + H1 * NP;       // H1 * NN

    const int tid = threadIdx.x;
    const int bid = blockIdx.x;

    const bool intra = (bid < BB * (NN / 4));
    int b, l = 0, i0;
    const float *gu, *gv, *w2d, *b2, *W3, *b3p;
    if (intra) {
        b  = bid / (NN / 4);
        i0 = (bid % (NN / 4)) * 4;
        gu = g_piA; gv = g_pjA; w2d = g_W2dup_i; b2 = bi2; W3 = Wi3; b3p = bi3;
    } else {
        const int e = bid - BB * (NN / 4);
        b = e / (LL * (NN / 4));
        const int r = e % (LL * (NN / 4));
        l  = r / (NN / 4);
        i0 = (r % (NN / 4)) * 4;
        gu = g_qiA; gv = g_qjA; w2d = g_W2dup_l; b2 = bl2; W3 = Wl3; b3p = bl3;
    }

    // Transposed pj load: s_pjT[k*NP + j]  (coalesced LDG, 4-way STS conflict)
    const float* pvb = gv + b * NN * H1;
    for (int idx = tid; idx < NN * H1; idx += 320) {
        const int j = idx >> 7;
        const int k = idx & (H1 - 1);
        s_pjT[k * NP + j] = pvb[idx];
    }
    __syncthreads();

    const int jt = tid >> 4;        // 0..19
    const int mt = tid & 15;        // 0..15
    const int j0 = jt * 8;
    const int m0 = mt * 4;

    // invariant per-thread epilogue constants
    float w3r[4];
    #pragma unroll
    for (int t = 0; t < 4; t++) w3r[t] = W3[m0 + t];
    unsigned long long b2p[4];
    #pragma unroll
    for (int t = 0; t < 4; t++) {
        const float bv = b2[m0 + t];
        asm("mov.b64 %0, {%1, %1};" : "=l"(b2p[t]) : "f"(bv));
    }
    const float b3 = b3p[0];

    for (int ii = 0; ii < 4; ii++) {
        const int i = i0 + ii;
        if (ii) __syncthreads();   // prev GEMM done reading s_h

        // ---- Phase A: h = relu(u + pj) into s_h ----
        {
            const float* gui = gu + (b * NN + i) * H1;
            // 320 threads x 16 steps over 5120 float4 (k-major: 40 float4/row)
            for (int t = tid; t < H1 * (NN / 4); t += 320) {
                const int k  = t / 40;
                const int j4 = t % 40;
                float u = gui[k];
                if (!intra) u += g_qlA[l * H1 + k];
                const float4 p = *(const float4*)(s_pjT + k * NP + j4 * 4);
                float4 hv;
                hv.x = fmaxf(u + p.x, 0.f);
                hv.y = fmaxf(u + p.y, 0.f);
                hv.z = fmaxf(u + p.z, 0.f);
                hv.w = fmaxf(u + p.w, 0.f);
                *(float4*)(s_h + k * NN + j4 * 4) = hv;
            }
        }
        __syncthreads();

        // ---- Phase B: j-packed GEMM ----
        unsigned long long acc[4][4];   // [jpair][m]
        #pragma unroll
        for (int jp = 0; jp < 4; jp++)
            #pragma unroll
            for (int m = 0; m < 4; m++) acc[jp][m] = b2p[m];

        const float* hp = s_h + j0;
        const float* wp = w2d + m0 * 2;
        #pragma unroll 4
        for (int k = 0; k < H1; k++) {
            const ulonglong2 h01 = *(const ulonglong2*)(hp);
            const ulonglong2 h23 = *(const ulonglong2*)(hp + 4);
            const ulonglong2 wd0 = *(const ulonglong2*)(wp);
            const ulonglong2 wd1 = *(const ulonglong2*)(wp + 4);
            hp += NN;
            wp += 2 * H2;
            const unsigned long long hv[4] = {h01.x, h01.y, h23.x, h23.y};
            const unsigned long long wv[4] = {wd0.x, wd0.y, wd1.x, wd1.y};
            #pragma unroll
            for (int jp = 0; jp < 4; jp++) {
                #pragma unroll
                for (int m = 0; m < 4; m++) {
                    asm("fma.rn.f32x2 %0, %1, %2, %0;"
                        : "+l"(acc[jp][m]) : "l"(hv[jp]), "l"(wv[m]));
                }
            }
        }

        // ---- epilogue: relu . W3, reduce over 16 mt lanes ----
        float part[8];
        #pragma unroll
        for (int jp = 0; jp < 4; jp++) {
            float le = 0.f, lo = 0.f;
            #pragma unroll
            for (int m = 0; m < 4; m++) {
                const float c0 = __uint_as_float((unsigned)acc[jp][m]);
                const float c1 = __uint_as_float((unsigned)(acc[jp][m] >> 32));
                le += fmaxf(c0, 0.f) * w3r[m];
                lo += fmaxf(c1, 0.f) * w3r[m];
            }
            part[2 * jp]     = le;
            part[2 * jp + 1] = lo;
        }
        #pragma unroll
        for (int jj = 0; jj < 8; jj++) {
            part[jj] += __shfl_xor_sync(0xFFFFFFFFu, part[jj], 1, 16);
            part[jj] += __shfl_xor_sync(0xFFFFFFFFu, part[jj], 2, 16);
            part[jj] += __shfl_xor_sync(0xFFFFFFFFu, part[jj], 4, 16);
            part[jj] += __shfl_xor_sync(0xFFFFFFFFu, part[jj], 8, 16);
        }

        if (mt < 8) {
            float lg = part[0];
            #pragma unroll
            for (int jj = 1; jj < 8; jj++)
                if (mt == jj) lg = part[jj];
            lg += b3;

            float sig = 1.f / (1.f + __expf(-lg));
            const int j = j0 + mt;
            if (i == j) sig = 0.f;

            size_t off;
            if (intra)
                off = ((size_t)(b * NN + i)) * NN + j;
            else
                off = (size_t)BB * NN * NN +
                      ((size_t)((b * LL + l) * NN) + i) * NN + j;
            out[off] = sig;
        }
    }
}

static const int PAIR_SMEM_BYTES = (H1 * NP + H1 * NN) * (int)sizeof(float);

extern "C" void kernel_launch(void* const* d_in, const int* in_sizes, int n_in,
                              void* d_out, int out_size)
{
    const float* ne  = (const float*)d_in[0];
    const float* zi  = (const float*)d_in[1];
    const float* ze  = (const float*)d_in[2];
    const float* lag = (const float*)d_in[3];
    const float* Wi1 = (const float*)d_in[4];
    const float* bi1 = (const float*)d_in[5];
    const float* Wi2 = (const float*)d_in[6];
    const float* bi2 = (const float*)d_in[7];
    const float* Wi3 = (const float*)d_in[8];
    const float* bi3 = (const float*)d_in[9];
    const float* Wl1 = (const float*)d_in[10];
    const float* bl1 = (const float*)d_in[11];
    const float* Wl2 = (const float*)d_in[12];
    const float* bl2 = (const float*)d_in[13];
    const float* Wl3 = (const float*)d_in[14];
    const float* bl3 = (const float*)d_in[15];
    float* out = (float*)d_out;

    cudaFuncSetAttribute(pair_kernel,
                         cudaFuncAttributeMaxDynamicSharedMemorySize,
                         PAIR_SMEM_BYTES);

    dup_kernel<<<32, 256>>>(Wi2, Wl2);
    proj_kernel<<<BB * NN, H1>>>(ne, zi, ze, lag, Wi1, bi1, Wl1, bl1);

    const int nblocks = BB * (NN / 4) + BB * LL * (NN / 4);  // 800
    pair_kernel<<<nblocks, 320, PAIR_SMEM_BYTES>>>(
        bi2, Wi3, bi3, bl2, Wl3, bl3, out);
}

// round 4
// speedup vs baseline: 1.4693x; 1.4693x over previous
#include <cuda_runtime.h>

#define BB 4
#define NN 160
#define DD 64
#define ZIc 64
#define ZEc 64
#define LL 4
#define LEc 8
#define H1 128
#define H2 64
#define NP 164   // padded pjT row stride

// Scratch (allocation-free: __device__ globals)
__device__ float g_piA[BB * NN * H1];
__device__ float g_pjA[BB * NN * H1];
__device__ float g_qiA[BB * NN * H1];
__device__ float g_qjA[BB * NN * H1];
__device__ float g_qlA[LL * H1];

// ---------------------------------------------------------------------------
// Kernel 1: per-(b,n) projections (tiny)
// ---------------------------------------------------------------------------
__global__ void proj_kernel(const float* __restrict__ ne,
                            const float* __restrict__ zi,
                            const float* __restrict__ ze,
                            const float* __restrict__ lag,
                            const float* __restrict__ Wi1,
                            const float* __restrict__ bi1,
                            const float* __restrict__ Wl1,
                            const float* __restrict__ bl1)
{
    __shared__ float s_ne[DD], s_zi[ZIc], s_ze[ZEc];
    const int bid = blockIdx.x;
    const int b   = bid / NN;
    const int k   = threadIdx.x;

    if (k < DD)  s_ne[k] = ne[bid * DD + k];
    if (k < ZIc) s_zi[k] = zi[b * ZIc + k];
    if (k < ZEc) s_ze[k] = ze[b * ZEc + k];
    __syncthreads();

    float api = bi1[k];
    float apj = 0.f;
    float aqi = bl1[k];
    float aqj = 0.f;

    #pragma unroll 8
    for (int d = 0; d < DD; d++) {
        const float nd = s_ne[d];
        api += nd * Wi1[d * H1 + k];
        apj += nd * Wi1[(DD + d) * H1 + k];
        aqi += nd * Wl1[d * H1 + k];
        aqj += nd * Wl1[(DD + d) * H1 + k];
    }
    #pragma unroll 8
    for (int z = 0; z < ZIc; z++) {
        api += s_zi[z] * Wi1[(2 * DD + z) * H1 + k];
        aqi += s_ze[z] * Wl1[(2 * DD + z) * H1 + k];
    }

    g_piA[bid * H1 + k] = api;
    g_pjA[bid * H1 + k] = apj;
    g_qiA[bid * H1 + k] = aqi;
    g_qjA[bid * H1 + k] = aqj;

    if (bid == 0) {
        #pragma unroll
        for (int l = 0; l < LL; l++) {
            float a = 0.f;
            #pragma unroll
            for (int e = 0; e < LEc; e++)
                a += lag[l * LEc + e] * Wl1[(2 * DD + ZEc + e) * H1 + k];
            g_qlA[l * H1 + k] = a;
        }
    }
}

// ---------------------------------------------------------------------------
// Kernel 2: pairwise MLP. Block = one (b,[l]) x 4 i's.
// Phase A (per i): s_h[k][j] = relu(u_i[k] + pjT[k][j])
// Phase B (per i): GEMM s_h x W2, thread tile 4j x 8m, m-packed f32x2 acc.
//   Warp-uniform W2 (smem broadcast LDS.128). h dup'd via 4 mov.b64/k.
// Mapping: warps 0-7: mt = w, jt = lane (0..31).
//          warps 8-9: idx = (w-8)*32+lane; jt = 32 + idx%8; mt = idx/8.
// ---------------------------------------------------------------------------
extern __shared__ float smem[];

__global__ __launch_bounds__(320, 1) void pair_kernel(
    const float* __restrict__ Wi2, const float* __restrict__ bi2,
    const float* __restrict__ Wi3, const float* __restrict__ bi3,
    const float* __restrict__ Wl2, const float* __restrict__ bl2,
    const float* __restrict__ Wl3, const float* __restrict__ bl3,
    float* __restrict__ out)
{
    float* s_pjT  = smem;                   // H1 * NP      (20992)
    float* s_h    = s_pjT + H1 * NP;        // H1 * NN      (20480)
    float* s_W2   = s_h + H1 * NN;          // H1 * H2      (8192)
    float* s_part = s_W2 + H1 * H2;         // 8 * NN       (1280)

    const int tid = threadIdx.x;
    const int bid = blockIdx.x;

    const bool intra = (bid < BB * (NN / 4));
    int b, l = 0, i0;
    const float *gu, *gv, *W2, *b2, *W3, *b3p;
    if (intra) {
        b  = bid / (NN / 4);
        i0 = (bid % (NN / 4)) * 4;
        gu = g_piA; gv = g_pjA; W2 = Wi2; b2 = bi2; W3 = Wi3; b3p = bi3;
    } else {
        const int e = bid - BB * (NN / 4);
        b = e / (LL * (NN / 4));
        const int r = e % (LL * (NN / 4));
        l  = r / (NN / 4);
        i0 = (r % (NN / 4)) * 4;
        gu = g_qiA; gv = g_qjA; W2 = Wl2; b2 = bl2; W3 = Wl3; b3p = bl3;
    }

    // Stage pjT (transposed) and W2 into smem
    const float* pvb = gv + b * NN * H1;
    for (int idx = tid; idx < NN * H1; idx += 320) {
        const int j = idx >> 7;
        const int k = idx & (H1 - 1);
        s_pjT[k * NP + j] = pvb[idx];
    }
    for (int idx = tid; idx < H1 * H2; idx += 320) s_W2[idx] = W2[idx];

    // thread mapping
    const int w    = tid >> 5;
    const int lane = tid & 31;
    int jt, mt;
    if (w < 8) { mt = w; jt = lane; }
    else { const int idx = (w - 8) * 32 + lane; jt = 32 + (idx & 7); mt = idx >> 3; }
    const int j0 = jt * 4;
    const int m0 = mt * 8;

    // epilogue constants
    float w3r[8];
    #pragma unroll
    for (int t = 0; t < 8; t++) w3r[t] = W3[m0 + t];
    ulonglong2 b2a = *(const ulonglong2*)(b2 + m0);
    ulonglong2 b2b = *(const ulonglong2*)(b2 + m0 + 4);
    const unsigned long long b2p[4] = {b2a.x, b2a.y, b2b.x, b2b.y};
    const float b3 = b3p[0];

    __syncthreads();

    for (int ii = 0; ii < 4; ii++) {
        const int i = i0 + ii;

        // ---- Phase A: s_h[k][j] = relu(u_i[k] + pjT[k][j]) ----
        {
            const float* gui = gu + (b * NN + i) * H1;
            for (int t = tid; t < H1 * (NN / 4); t += 320) {
                const int k  = t / 40;
                const int j4 = t % 40;
                float u = gui[k];
                if (!intra) u += g_qlA[l * H1 + k];
                const float4 p = *(const float4*)(s_pjT + k * NP + j4 * 4);
                float4 hv;
                hv.x = fmaxf(u + p.x, 0.f);
                hv.y = fmaxf(u + p.y, 0.f);
                hv.z = fmaxf(u + p.z, 0.f);
                hv.w = fmaxf(u + p.w, 0.f);
                *(float4*)(s_h + k * NN + j4 * 4) = hv;
            }
        }
        __syncthreads();

        // ---- Phase B: m-packed GEMM, warp-uniform W2 ----
        unsigned long long acc[4][4];   // [j][m-pair]
        #pragma unroll
        for (int jj = 0; jj < 4; jj++)
            #pragma unroll
            for (int mp = 0; mp < 4; mp++) acc[jj][mp] = b2p[mp];

        const float* hp = s_h + j0;
        const float* wp = s_W2 + m0;
        #pragma unroll 4
        for (int k = 0; k < H1; k++) {
            const float4 hq = *(const float4*)(hp);
            const ulonglong2 wa = *(const ulonglong2*)(wp);
            const ulonglong2 wb = *(const ulonglong2*)(wp + 4);
            hp += NN;
            wp += H2;
            const unsigned long long wv[4] = {wa.x, wa.y, wb.x, wb.y};
            unsigned long long hd[4];
            asm("mov.b64 %0, {%1, %1};" : "=l"(hd[0]) : "f"(hq.x));
            asm("mov.b64 %0, {%1, %1};" : "=l"(hd[1]) : "f"(hq.y));
            asm("mov.b64 %0, {%1, %1};" : "=l"(hd[2]) : "f"(hq.z));
            asm("mov.b64 %0, {%1, %1};" : "=l"(hd[3]) : "f"(hq.w));
            #pragma unroll
            for (int jj = 0; jj < 4; jj++) {
                #pragma unroll
                for (int mp = 0; mp < 4; mp++) {
                    asm("fma.rn.f32x2 %0, %1, %2, %0;"
                        : "+l"(acc[jj][mp]) : "l"(hd[jj]), "l"(wv[mp]));
                }
            }
        }

        // ---- epilogue part 1: relu . W3 per (j, mt) ----
        #pragma unroll
        for (int jj = 0; jj < 4; jj++) {
            float lg = 0.f;
            #pragma unroll
            for (int mp = 0; mp < 4; mp++) {
                const float c0 = __uint_as_float((unsigned)acc[jj][mp]);
                const float c1 = __uint_as_float((unsigned)(acc[jj][mp] >> 32));
                lg += fmaxf(c0, 0.f) * w3r[2 * mp];
                lg += fmaxf(c1, 0.f) * w3r[2 * mp + 1];
            }
            s_part[mt * NN + j0 + jj] = lg;
        }
        __syncthreads();

        // ---- epilogue part 2: reduce 8 mt groups, sigmoid, store ----
        if (tid < NN) {
            const int j = tid;
            float lg = b3;
            #pragma unroll
            for (int m = 0; m < 8; m++) lg += s_part[m * NN + j];
            float sig = 1.f / (1.f + __expf(-lg));
            if (i == j) sig = 0.f;
            size_t off;
            if (intra)
                off = ((size_t)(b * NN + i)) * NN + j;
            else
                off = (size_t)BB * NN * NN +
                      ((size_t)((b * LL + l) * NN) + i) * NN + j;
            out[off] = sig;
        }
        __syncthreads();   // s_h / s_part reuse for next i
    }
}

static const int PAIR_SMEM_BYTES =
    (H1 * NP + H1 * NN + H1 * H2 + 8 * NN) * (int)sizeof(float);

extern "C" void kernel_launch(void* const* d_in, const int* in_sizes, int n_in,
                              void* d_out, int out_size)
{
    const float* ne  = (const float*)d_in[0];
    const float* zi  = (const float*)d_in[1];
    const float* ze  = (const float*)d_in[2];
    const float* lag = (const float*)d_in[3];
    const float* Wi1 = (const float*)d_in[4];
    const float* bi1 = (const float*)d_in[5];
    const float* Wi2 = (const float*)d_in[6];
    const float* bi2 = (const float*)d_in[7];
    const float* Wi3 = (const float*)d_in[8];
    const float* bi3 = (const float*)d_in[9];
    const float* Wl1 = (const float*)d_in[10];
    const float* bl1 = (const float*)d_in[11];
    const float* Wl2 = (const float*)d_in[12];
    const float* bl2 = (const float*)d_in[13];
    const float* Wl3 = (const float*)d_in[14];
    const float* bl3 = (const float*)d_in[15];
    float* out = (float*)d_out;

    cudaFuncSetAttribute(pair_kernel,
                         cudaFuncAttributeMaxDynamicSharedMemorySize,
                         PAIR_SMEM_BYTES);

    proj_kernel<<<BB * NN, H1>>>(ne, zi, ze, lag, Wi1, bi1, Wl1, bl1);

    const int nblocks = BB * (NN / 4) + BB * LL * (NN / 4);  // 800
    pair_kernel<<<nblocks, 320, PAIR_SMEM_BYTES>>>(
        Wi2, bi2, Wi3, bi3, Wl2, bl2, Wl3, bl3, out);
}

// round 5
// speedup vs baseline: 1.4855x; 1.0110x over previous
#include <cuda_runtime.h>

#define BB 4
#define NN 160
#define DD 64
#define ZIc 64
#define ZEc 64
#define LL 4
#define LEc 8
#define H1 128
#define H2 64
#define KH 64          // k half
#define PJ 65          // s_pj row pad (conflict-free scalar LDS/STS)

// Scratch (allocation-free: __device__ globals)
__device__ float g_piA[BB * NN * H1];
__device__ float g_pjA[BB * NN * H1];
__device__ float g_qiA[BB * NN * H1];
__device__ float g_qjA[BB * NN * H1];
__device__ float g_qlA[LL * H1];

// ---------------------------------------------------------------------------
// Kernel 1: per-(b,n) projections (tiny)
// ---------------------------------------------------------------------------
__global__ void proj_kernel(const float* __restrict__ ne,
                            const float* __restrict__ zi,
                            const float* __restrict__ ze,
                            const float* __restrict__ lag,
                            const float* __restrict__ Wi1,
                            const float* __restrict__ bi1,
                            const float* __restrict__ Wl1,
                            const float* __restrict__ bl1)
{
    __shared__ float s_ne[DD], s_zi[ZIc], s_ze[ZEc];
    const int bid = blockIdx.x;
    const int b   = bid / NN;
    const int k   = threadIdx.x;

    if (k < DD)  s_ne[k] = ne[bid * DD + k];
    if (k < ZIc) s_zi[k] = zi[b * ZIc + k];
    if (k < ZEc) s_ze[k] = ze[b * ZEc + k];
    __syncthreads();

    float api = bi1[k];
    float apj = 0.f;
    float aqi = bl1[k];
    float aqj = 0.f;

    #pragma unroll 8
    for (int d = 0; d < DD; d++) {
        const float nd = s_ne[d];
        api += nd * Wi1[d * H1 + k];
        apj += nd * Wi1[(DD + d) * H1 + k];
        aqi += nd * Wl1[d * H1 + k];
        aqj += nd * Wl1[(DD + d) * H1 + k];
    }
    #pragma unroll 8
    for (int z = 0; z < ZIc; z++) {
        api += s_zi[z] * Wi1[(2 * DD + z) * H1 + k];
        aqi += s_ze[z] * Wl1[(2 * DD + z) * H1 + k];
    }

    g_piA[bid * H1 + k] = api;
    g_pjA[bid * H1 + k] = apj;
    g_qiA[bid * H1 + k] = aqi;
    g_qjA[bid * H1 + k] = aqj;

    if (bid == 0) {
        #pragma unroll
        for (int l = 0; l < LL; l++) {
            float a = 0.f;
            #pragma unroll
            for (int e = 0; e < LEc; e++)
                a += lag[l * LEc + e] * Wl1[(2 * DD + ZEc + e) * H1 + k];
            g_qlA[l * H1 + k] = a;
        }
    }
}

// ---------------------------------------------------------------------------
// Kernel 2: pairwise MLP, k-split in halves for 2-block/SM residency.
// Per block: one (b,[l]) x 4 i's. Per (i,kh):
//   load s_pj (j-major, pad 65) + s_W2 half
//   Phase A: s_h[kk][j] = relu(u[k] + pj[j][k])   (conflict-free LDS+STS)
//   Phase B: acc += s_h x W2half  (4j x 8m m-packed f32x2, uniform W2)
// Mapping: warps 0-7: mt=w, jt=lane; warps 8-9: jt=32+idx%8, mt=idx/8.
// ---------------------------------------------------------------------------
extern __shared__ float smem[];

__global__ __launch_bounds__(320, 2) void pair_kernel(
    const float* __restrict__ Wi2, const float* __restrict__ bi2,
    const float* __restrict__ Wi3, const float* __restrict__ bi3,
    const float* __restrict__ Wl2, const float* __restrict__ bl2,
    const float* __restrict__ Wl3, const float* __restrict__ bl3,
    float* __restrict__ out)
{
    float* s_pj   = smem;                   // NN * PJ   (10400)
    float* s_h    = s_pj + NN * PJ;         // KH * NN   (10240)
    float* s_W2   = s_h + KH * NN;          // KH * H2   (4096)
    float* s_part = s_W2 + KH * H2;         // 8 * NN    (1280)

    const int tid = threadIdx.x;
    const int bid = blockIdx.x;

    const bool intra = (bid < BB * (NN / 4));
    int b, l = 0, i0;
    const float *gu, *gv, *W2, *b2, *W3, *b3p;
    if (intra) {
        b  = bid / (NN / 4);
        i0 = (bid % (NN / 4)) * 4;
        gu = g_piA; gv = g_pjA; W2 = Wi2; b2 = bi2; W3 = Wi3; b3p = bi3;
    } else {
        const int e = bid - BB * (NN / 4);
        b = e / (LL * (NN / 4));
        const int r = e % (LL * (NN / 4));
        l  = r / (NN / 4);
        i0 = (r % (NN / 4)) * 4;
        gu = g_qiA; gv = g_qjA; W2 = Wl2; b2 = bl2; W3 = Wl3; b3p = bl3;
    }

    // thread mapping for Phase B
    const int w    = tid >> 5;
    const int lane = tid & 31;
    int jt, mt;
    if (w < 8) { mt = w; jt = lane; }
    else { const int idx = (w - 8) * 32 + lane; jt = 32 + (idx & 7); mt = idx >> 3; }
    const int j0 = jt * 4;
    const int m0 = mt * 8;

    // Phase A mapping
    const int ja    = tid % 160;          // j (lanes consecutive)
    const int kbase = (tid / 160) * 32;   // this team's kk range

    // epilogue constants
    float w3r[8];
    #pragma unroll
    for (int t = 0; t < 8; t++) w3r[t] = W3[m0 + t];
    ulonglong2 b2a = *(const ulonglong2*)(b2 + m0);
    ulonglong2 b2b = *(const ulonglong2*)(b2 + m0 + 4);
    const unsigned long long b2p[4] = {b2a.x, b2a.y, b2b.x, b2b.y};
    const float b3 = b3p[0];

    for (int ii = 0; ii < 4; ii++) {
        const int i = i0 + ii;

        unsigned long long acc[4][4];   // [j][m-pair]
        #pragma unroll
        for (int jj = 0; jj < 4; jj++)
            #pragma unroll
            for (int mp = 0; mp < 4; mp++) acc[jj][mp] = b2p[mp];

        for (int kh = 0; kh < 2; kh++) {
            __syncthreads();   // previous readers of s_pj/s_h/s_W2 done

            // ---- stage s_pj (this b, this k-half) + s_W2 half ----
            const float* pvb = gv + b * NN * H1 + kh * KH;
            for (int t = tid; t < NN * KH; t += 320) {
                const int j  = t >> 6;
                const int kk = t & (KH - 1);
                s_pj[j * PJ + kk] = pvb[j * H1 + kk];
            }
            const float* wsrc = W2 + kh * KH * H2;
            for (int t = tid; t < KH * H2; t += 320) s_W2[t] = wsrc[t];
            __syncthreads();

            // ---- Phase A: s_h[kk][j] = relu(u + pj) ----
            {
                const float* gui = gu + (b * NN + i) * H1 + kh * KH + kbase;
                const float* qlp = g_qlA + l * H1 + kh * KH + kbase;
                const float* pjr = s_pj + ja * PJ + kbase;
                float* hw = s_h + kbase * NN + ja;
                #pragma unroll 4
                for (int r = 0; r < 32; r++) {
                    float u = gui[r];
                    if (!intra) u += qlp[r];
                    hw[r * NN] = fmaxf(u + pjr[r], 0.f);
                }
            }
            __syncthreads();

            // ---- Phase B: accumulate ----
            const float* hp = s_h + j0;
            const float* wp = s_W2 + m0;
            #pragma unroll 4
            for (int kk = 0; kk < KH; kk++) {
                const float4 hq = *(const float4*)(hp);
                const ulonglong2 wa = *(const ulonglong2*)(wp);
                const ulonglong2 wb = *(const ulonglong2*)(wp + 4);
                hp += NN;
                wp += H2;
                const unsigned long long wv[4] = {wa.x, wa.y, wb.x, wb.y};
                unsigned long long hd[4];
                asm("mov.b64 %0, {%1, %1};" : "=l"(hd[0]) : "f"(hq.x));
                asm("mov.b64 %0, {%1, %1};" : "=l"(hd[1]) : "f"(hq.y));
                asm("mov.b64 %0, {%1, %1};" : "=l"(hd[2]) : "f"(hq.z));
                asm("mov.b64 %0, {%1, %1};" : "=l"(hd[3]) : "f"(hq.w));
                #pragma unroll
                for (int jj = 0; jj < 4; jj++) {
                    #pragma unroll
                    for (int mp = 0; mp < 4; mp++) {
                        asm("fma.rn.f32x2 %0, %1, %2, %0;"
                            : "+l"(acc[jj][mp]) : "l"(hd[jj]), "l"(wv[mp]));
                    }
                }
            }
        }

        // ---- epilogue part 1: relu . W3 per (j, mt) ----
        #pragma unroll
        for (int jj = 0; jj < 4; jj++) {
            float lg = 0.f;
            #pragma unroll
            for (int mp = 0; mp < 4; mp++) {
                const float c0 = __uint_as_float((unsigned)acc[jj][mp]);
                const float c1 = __uint_as_float((unsigned)(acc[jj][mp] >> 32));
                lg += fmaxf(c0, 0.f) * w3r[2 * mp];
                lg += fmaxf(c1, 0.f) * w3r[2 * mp + 1];
            }
            s_part[mt * NN + j0 + jj] = lg;
        }
        __syncthreads();

        // ---- epilogue part 2: reduce 8 mt groups, sigmoid, store ----
        if (tid < NN) {
            const int j = tid;
            float lg = b3;
            #pragma unroll
            for (int m = 0; m < 8; m++) lg += s_part[m * NN + j];
            float sig = 1.f / (1.f + __expf(-lg));
            if (i == j) sig = 0.f;
            size_t off;
            if (intra)
                off = ((size_t)(b * NN + i)) * NN + j;
            else
                off = (size_t)BB * NN * NN +
                      ((size_t)((b * LL + l) * NN) + i) * NN + j;
            out[off] = sig;
        }
    }
}

static const int PAIR_SMEM_BYTES =
    (NN * PJ + KH * NN + KH * H2 + 8 * NN) * (int)sizeof(float);

extern "C" void kernel_launch(void* const* d_in, const int* in_sizes, int n_in,
                              void* d_out, int out_size)
{
    const float* ne  = (const float*)d_in[0];
    const float* zi  = (const float*)d_in[1];
    const float* ze  = (const float*)d_in[2];
    const float* lag = (const float*)d_in[3];
    const float* Wi1 = (const float*)d_in[4];
    const float* bi1 = (const float*)d_in[5];
    const float* Wi2 = (const float*)d_in[6];
    const float* bi2 = (const float*)d_in[7];
    const float* Wi3 = (const float*)d_in[8];
    const float* bi3 = (const float*)d_in[9];
    const float* Wl1 = (const float*)d_in[10];
    const float* bl1 = (const float*)d_in[11];
    const float* Wl2 = (const float*)d_in[12];
    const float* bl2 = (const float*)d_in[13];
    const float* Wl3 = (const float*)d_in[14];
    const float* bl3 = (const float*)d_in[15];
    float* out = (float*)d_out;

    cudaFuncSetAttribute(pair_kernel,
                         cudaFuncAttributeMaxDynamicSharedMemorySize,
                         PAIR_SMEM_BYTES);

    proj_kernel<<<BB * NN, H1>>>(ne, zi, ze, lag, Wi1, bi1, Wl1, bl1);

    const int nblocks = BB * (NN / 4) + BB * LL * (NN / 4);  // 800
    pair_kernel<<<nblocks, 320, PAIR_SMEM_BYTES>>>(
        Wi2, bi2, Wi3, bi3, Wl2, bl2, Wl3, bl3, out);
}

// round 7
// speedup vs baseline: 3.9219x; 2.6401x over previous
#include <cuda_runtime.h>
#include <cstdint>

#define BB 4
#define NN 160
#define DD 64
#define ZIc 64
#define ZEc 64
#define LL 4
#define LEc 8
#define H1 128
#define H2 64
#define HS 132   // h row stride (mod 32 == 4 -> conflict-free B-frag LDS)

// ---------------- device scratch (allocation-free) ----------------
__device__ float g_piA[BB * NN * H1];
__device__ float g_pjA[BB * NN * H1];
__device__ float g_qiA[BB * NN * H1];
__device__ float g_qjA[BB * NN * H1];
__device__ float g_qlA[LL * H1];

__device__ __forceinline__ uint32_t f2tf(float f) {
    uint32_t r;
    asm("cvt.rna.tf32.f32 %0, %1;" : "=r"(r) : "f"(f));
    return r;
}

__device__ __forceinline__ void mma_tf32(float& d0, float& d1, float& d2, float& d3,
                                         uint32_t a0, uint32_t a1, uint32_t a2, uint32_t a3,
                                         uint32_t b0, uint32_t b1) {
    asm volatile(
        "mma.sync.aligned.m16n8k8.row.col.f32.tf32.tf32.f32 "
        "{%0,%1,%2,%3}, {%4,%5,%6,%7}, {%8,%9}, {%0,%1,%2,%3};"
        : "+f"(d0), "+f"(d1), "+f"(d2), "+f"(d3)
        : "r"(a0), "r"(a1), "r"(a2), "r"(a3), "r"(b0), "r"(b1));
}

// ---------------------------------------------------------------------------
// Kernel 1: per-(b,n) projections (tiny)
// ---------------------------------------------------------------------------
__global__ void proj_kernel(const float* __restrict__ ne,
                            const float* __restrict__ zi,
                            const float* __restrict__ ze,
                            const float* __restrict__ lag,
                            const float* __restrict__ Wi1,
                            const float* __restrict__ bi1,
                            const float* __restrict__ Wl1,
                            const float* __restrict__ bl1)
{
    __shared__ float s_ne[DD], s_zi[ZIc], s_ze[ZEc];
    const int bid = blockIdx.x;
    const int b   = bid / NN;
    const int k   = threadIdx.x;

    if (k < DD)  s_ne[k] = ne[bid * DD + k];
    if (k < ZIc) s_zi[k] = zi[b * ZIc + k];
    if (k < ZEc) s_ze[k] = ze[b * ZEc + k];
    __syncthreads();

    float api = bi1[k];
    float apj = 0.f;
    float aqi = bl1[k];
    float aqj = 0.f;

    #pragma unroll 8
    for (int d = 0; d < DD; d++) {
        const float nd = s_ne[d];
        api += nd * Wi1[d * H1 + k];
        apj += nd * Wi1[(DD + d) * H1 + k];
        aqi += nd * Wl1[d * H1 + k];
        aqj += nd * Wl1[(DD + d) * H1 + k];
    }
    #pragma unroll 8
    for (int z = 0; z < ZIc; z++) {
        api += s_zi[z] * Wi1[(2 * DD + z) * H1 + k];
        aqi += s_ze[z] * Wl1[(2 * DD + z) * H1 + k];
    }

    g_piA[bid * H1 + k] = api;
    g_pjA[bid * H1 + k] = apj;
    g_qiA[bid * H1 + k] = aqi;
    g_qjA[bid * H1 + k] = aqj;

    if (bid == 0) {
        #pragma unroll
        for (int l = 0; l < LL; l++) {
            float a = 0.f;
            #pragma unroll
            for (int e = 0; e < LEc; e++)
                a += lag[l * LEc + e] * Wl1[(2 * DD + ZEc + e) * H1 + k];
            g_qlA[l * H1 + k] = a;
        }
    }
}

// ---------------------------------------------------------------------------
// Kernel 2: pairwise MLP via mma.sync tf32 (HMMA).
// Block = one (b,[l]) x 4 i's, 256 thr = 8 warps.
// A operand = W2^T (64m x 128k), 4 m-tiles of 16; warp (mg = w&3) holds its
//   m-tile's A-fragments in 64 regs, loaded once per block.
// B operand = h (k x j), warp covers n-half (nh = w>>2): 10 n-tiles of 8 j.
// Per i: Phase A stages h[j][k] (tf32-rounded) into smem stride 132;
//   then per n-tile: 16 HMMAs (2 conflict-free LDS each) + in-reg epilogue
//   (relu(d+b2)*W3, shfl-reduce over m within warp) -> s_part[mg][j];
//   final pass: sum 4 mg-partials + b3, sigmoid, mask, store.
// ---------------------------------------------------------------------------
extern __shared__ float smem[];

__global__ __launch_bounds__(256, 2) void pair_mma_kernel(
    const float* __restrict__ Wi2, const float* __restrict__ bi2,
    const float* __restrict__ Wi3, const float* __restrict__ bi3,
    const float* __restrict__ Wl2, const float* __restrict__ bl2,
    const float* __restrict__ Wl3, const float* __restrict__ bl3,
    float* __restrict__ out)
{
    float* s_h    = smem;               // NN * HS = 21120 floats
    float* s_part = s_h + NN * HS;      // 4 * NN  = 640 floats

    const int tid  = threadIdx.x;
    const int wid  = tid >> 5;
    const int lane = tid & 31;
    const int bid  = blockIdx.x;

    const bool intra = (bid < BB * (NN / 4));
    int b, l = 0, i0;
    const float *gu, *gv, *W2, *b2, *W3, *b3p;
    if (intra) {
        b  = bid / (NN / 4);
        i0 = (bid % (NN / 4)) * 4;
        gu = g_piA; gv = g_pjA; W2 = Wi2; b2 = bi2; W3 = Wi3; b3p = bi3;
    } else {
        const int e = bid - BB * (NN / 4);
        b = e / (LL * (NN / 4));
        const int r = e % (LL * (NN / 4));
        l  = r / (NN / 4);
        i0 = (r % (NN / 4)) * 4;
        gu = g_qiA; gv = g_qjA; W2 = Wl2; b2 = bl2; W3 = Wl3; b3p = bl3;
    }

    const int g  = lane >> 2;     // 0..7
    const int q  = lane & 3;      // 0..3
    const int mg = wid & 3;       // m-tile
    const int nh = wid >> 1 >> 1; // 0..1 (wid>>2)
    const int m0 = mg * 16;
    const int nbase = nh * 80;

    // ---- A fragments: W2T[m0..m0+15][0..127], tf32-rounded, once per block ----
    uint32_t af[16][4];
    #pragma unroll
    for (int kt = 0; kt < 16; kt++) {
        const int k0 = kt * 8 + q;
        af[kt][0] = f2tf(W2[k0 * H2 + m0 + g]);
        af[kt][1] = f2tf(W2[k0 * H2 + m0 + g + 8]);
        af[kt][2] = f2tf(W2[(k0 + 4) * H2 + m0 + g]);
        af[kt][3] = f2tf(W2[(k0 + 4) * H2 + m0 + g + 8]);
    }

    // epilogue per-thread constants
    const float c2a = b2[m0 + g];
    const float w3a = W3[m0 + g];
    const float c2b = b2[m0 + g + 8];
    const float w3b = W3[m0 + g + 8];
    const float b3  = b3p[0];

    const float* pvb = gv + b * NN * H1;
    const float* qlp = g_qlA + l * H1;

    for (int ii = 0; ii < 4; ii++) {
        const int i = i0 + ii;
        __syncthreads();   // prev final-store readers done; s_h free

        // ---- Phase A: s_h[j][k] = tf32(relu(u_i[k] + pj[j][k])) ----
        {
            const float* gui = gu + (b * NN + i) * H1;
            #pragma unroll 4
            for (int t = tid; t < NN * 32; t += 256) {
                const int j  = t >> 5;
                const int k4 = (t & 31) * 4;
                float4 u4 = *(const float4*)(gui + k4);
                if (!intra) {
                    const float4 q4 = *(const float4*)(qlp + k4);
                    u4.x += q4.x; u4.y += q4.y; u4.z += q4.z; u4.w += q4.w;
                }
                const float4 p4 = *(const float4*)(pvb + j * H1 + k4);
                float4 hv;
                hv.x = __uint_as_float(f2tf(fmaxf(u4.x + p4.x, 0.f)));
                hv.y = __uint_as_float(f2tf(fmaxf(u4.y + p4.y, 0.f)));
                hv.z = __uint_as_float(f2tf(fmaxf(u4.z + p4.z, 0.f)));
                hv.w = __uint_as_float(f2tf(fmaxf(u4.w + p4.w, 0.f)));
                *(float4*)(s_h + j * HS + k4) = hv;
            }
        }
        __syncthreads();

        // ---- MMA + fused epilogue per n-tile ----
        #pragma unroll 1
        for (int nt = 0; nt < 10; nt++) {
            const int n0 = nbase + nt * 8;
            float d0 = 0.f, d1 = 0.f, d2 = 0.f, d3 = 0.f;
            const uint32_t* hrow =
                (const uint32_t*)(s_h + (n0 + g) * HS + q);
            #pragma unroll
            for (int kt = 0; kt < 16; kt++) {
                const uint32_t b0v = hrow[kt * 8];
                const uint32_t b1v = hrow[kt * 8 + 4];
                mma_tf32(d0, d1, d2, d3,
                         af[kt][0], af[kt][1], af[kt][2], af[kt][3],
                         b0v, b1v);
            }
            // relu(d + b2[m]) * W3[m]; fold the two m-rows this thread holds
            const float e0 = fmaxf(d0 + c2a, 0.f) * w3a;
            const float e1 = fmaxf(d1 + c2a, 0.f) * w3a;
            const float e2 = fmaxf(d2 + c2b, 0.f) * w3b;
            const float e3 = fmaxf(d3 + c2b, 0.f) * w3b;
            float p0 = e0 + e2;   // col n0 + 2q
            float p1 = e1 + e3;   // col n0 + 2q + 1
            // reduce over g (8 lanes, stride 4)
            p0 += __shfl_xor_sync(0xFFFFFFFFu, p0, 4);
            p0 += __shfl_xor_sync(0xFFFFFFFFu, p0, 8);
            p0 += __shfl_xor_sync(0xFFFFFFFFu, p0, 16);
            p1 += __shfl_xor_sync(0xFFFFFFFFu, p1, 4);
            p1 += __shfl_xor_sync(0xFFFFFFFFu, p1, 8);
            p1 += __shfl_xor_sync(0xFFFFFFFFu, p1, 16);
            if (g == 0) {
                s_part[mg * NN + n0 + 2 * q]     = p0;
                s_part[mg * NN + n0 + 2 * q + 1] = p1;
            }
        }
        __syncthreads();

        // ---- final: sum 4 mg partials, sigmoid, mask, store ----
        if (tid < NN) {
            const int j = tid;
            const float lg = b3 + s_part[j] + s_part[NN + j]
                           + s_part[2 * NN + j] + s_part[3 * NN + j];
            float sig = 1.f / (1.f + __expf(-lg));
            if (i == j) sig = 0.f;
            size_t off;
            if (intra)
                off = ((size_t)(b * NN + i)) * NN + j;
            else
                off = (size_t)BB * NN * NN +
                      ((size_t)((b * LL + l) * NN) + i) * NN + j;
            out[off] = sig;
        }
    }
}

static const int PAIR_SMEM_BYTES = (NN * HS + 4 * NN) * (int)sizeof(float);

extern "C" void kernel_launch(void* const* d_in, const int* in_sizes, int n_in,
                              void* d_out, int out_size)
{
    const float* ne  = (const float*)d_in[0];
    const float* zi  = (const float*)d_in[1];
    const float* ze  = (const float*)d_in[2];
    const float* lag = (const float*)d_in[3];
    const float* Wi1 = (const float*)d_in[4];
    const float* bi1 = (const float*)d_in[5];
    const float* Wi2 = (const float*)d_in[6];
    const float* bi2 = (const float*)d_in[7];
    const float* Wi3 = (const float*)d_in[8];
    const float* bi3 = (const float*)d_in[9];
    const float* Wl1 = (const float*)d_in[10];
    const float* bl1 = (const float*)d_in[11];
    const float* Wl2 = (const float*)d_in[12];
    const float* bl2 = (const float*)d_in[13];
    const float* Wl3 = (const float*)d_in[14];
    const float* bl3 = (const float*)d_in[15];
    float* out = (float*)d_out;

    cudaFuncSetAttribute(pair_mma_kernel,
                         cudaFuncAttributeMaxDynamicSharedMemorySize,
                         PAIR_SMEM_BYTES);

    proj_kernel<<<BB * NN, H1>>>(ne, zi, ze, lag, Wi1, bi1, Wl1, bl1);

    const int nblocks = BB * (NN / 4) + BB * LL * (NN / 4);  // 800
    pair_mma_kernel<<<nblocks, 256, PAIR_SMEM_BYTES>>>(
        Wi2, bi2, Wi3, bi3, Wl2, bl2, Wl3, bl3, out);
}

// round 10
// speedup vs baseline: 5.0386x; 1.2847x over previous
#include <cuda_runtime.h>
#include <cuda_fp16.h>
#include <cstdint>

#define BB 4
#define NN 160
#define DD 64
#define ZIc 64
#define ZEc 64
#define LL 4
#define LEc 8
#define H1 128
#define H2 64
#define ST 68   // s_h row stride in 32-bit words (64 data + 4 pad; ST%32==4)

// ---------------- device scratch (allocation-free) ----------------
__device__ float g_piA[BB * NN * H1];
__device__ float g_pjA[BB * NN * H1];
__device__ float g_qiA[BB * NN * H1];
__device__ float g_qjA[BB * NN * H1];
__device__ float g_qlA[LL * H1];

__device__ __forceinline__ uint32_t h2u(__half2 h) {
    return *reinterpret_cast<uint32_t*>(&h);
}

__device__ __forceinline__ void mma_f16(float& d0, float& d1, float& d2, float& d3,
                                        uint32_t a0, uint32_t a1, uint32_t a2, uint32_t a3,
                                        uint32_t b0, uint32_t b1) {
    asm volatile(
        "mma.sync.aligned.m16n8k16.row.col.f32.f16.f16.f32 "
        "{%0,%1,%2,%3}, {%4,%5,%6,%7}, {%8,%9}, {%0,%1,%2,%3};"
        : "+f"(d0), "+f"(d1), "+f"(d2), "+f"(d3)
        : "r"(a0), "r"(a1), "r"(a2), "r"(a3), "r"(b0), "r"(b1));
}

// ---------------------------------------------------------------------------
// Kernel 1: per-(b,n) projections (tiny)
// ---------------------------------------------------------------------------
__global__ void proj_kernel(const float* __restrict__ ne,
                            const float* __restrict__ zi,
                            const float* __restrict__ ze,
                            const float* __restrict__ lag,
                            const float* __restrict__ Wi1,
                            const float* __restrict__ bi1,
                            const float* __restrict__ Wl1,
                            const float* __restrict__ bl1)
{
    __shared__ float s_ne[DD], s_zi[ZIc], s_ze[ZEc];
    const int bid = blockIdx.x;
    const int b   = bid / NN;
    const int k   = threadIdx.x;

    if (k < DD)  s_ne[k] = ne[bid * DD + k];
    if (k < ZIc) s_zi[k] = zi[b * ZIc + k];
    if (k < ZEc) s_ze[k] = ze[b * ZEc + k];
    __syncthreads();

    float api = bi1[k];
    float apj = 0.f;
    float aqi = bl1[k];
    float aqj = 0.f;

    #pragma unroll 8
    for (int d = 0; d < DD; d++) {
        const float nd = s_ne[d];
        api += nd * Wi1[d * H1 + k];
        apj += nd * Wi1[(DD + d) * H1 + k];
        aqi += nd * Wl1[d * H1 + k];
        aqj += nd * Wl1[(DD + d) * H1 + k];
    }
    #pragma unroll 8
    for (int z = 0; z < ZIc; z++) {
        api += s_zi[z] * Wi1[(2 * DD + z) * H1 + k];
        aqi += s_ze[z] * Wl1[(2 * DD + z) * H1 + k];
    }

    g_piA[bid * H1 + k] = api;
    g_pjA[bid * H1 + k] = apj;
    g_qiA[bid * H1 + k] = aqi;
    g_qjA[bid * H1 + k] = aqj;

    if (bid == 0) {
        #pragma unroll
        for (int l = 0; l < LL; l++) {
            float a = 0.f;
            #pragma unroll
            for (int e = 0; e < LEc; e++)
                a += lag[l * LEc + e] * Wl1[(2 * DD + ZEc + e) * H1 + k];
            g_qlA[l * H1 + k] = a;
        }
    }
}

// ---------------------------------------------------------------------------
// Kernel 2: pairwise MLP via mma.sync fp16 m16n8k16.
// Block = one (b,[l]) x 4 i's, 256 thr = 8 warps.
//   warp: mg = wid&1 (m-half: 2 m-tiles of 16), jg = wid>>1 (40 j = 5 n-tiles).
// A = W2^T fp16 fragments in regs (64 regs), loaded once per block.
// B = h (k x j) as half2-packed smem rows (stride 68 words, conflict-free).
// Per i: Phase A stage h; per n-tile: 8 kt x 2 mt HMMA + fused epilogue
//   (relu(d+b2)*W3, shfl-reduce over g) -> s_part[mg][j]; final sigmoid pass.
// ---------------------------------------------------------------------------
extern __shared__ uint32_t smemw[];

__global__ __launch_bounds__(256, 2) void pair_mma_kernel(
    const float* __restrict__ Wi2, const float* __restrict__ bi2,
    const float* __restrict__ Wi3, const float* __restrict__ bi3,
    const float* __restrict__ Wl2, const float* __restrict__ bl2,
    const float* __restrict__ Wl3, const float* __restrict__ bl3,
    float* __restrict__ out)
{
    uint32_t* s_h    = smemw;                       // NN * ST words
    float*    s_part = (float*)(smemw + NN * ST);   // 2 * NN floats

    const int tid  = threadIdx.x;
    const int wid  = tid >> 5;
    const int lane = tid & 31;
    const int bid  = blockIdx.x;

    const bool intra = (bid < BB * (NN / 4));
    int b, l = 0, i0;
    const float *gu, *gv, *W2, *b2, *W3, *b3p;
    if (intra) {
        b  = bid / (NN / 4);
        i0 = (bid % (NN / 4)) * 4;
        gu = g_piA; gv = g_pjA; W2 = Wi2; b2 = bi2; W3 = Wi3; b3p = bi3;
    } else {
        const int e = bid - BB * (NN / 4);
        b = e / (LL * (NN / 4));
        const int r = e % (LL * (NN / 4));
        l  = r / (NN / 4);
        i0 = (r % (NN / 4)) * 4;
        gu = g_qiA; gv = g_qjA; W2 = Wl2; b2 = bl2; W3 = Wl3; b3p = bl3;
    }

    const int g  = lane >> 2;     // 0..7
    const int q  = lane & 3;      // 0..3
    const int mg = wid & 1;       // m-half
    const int jg = wid >> 1;      // 0..3
    const int m0 = mg * 32;

    // ---- A fragments: W2T[m0..m0+31][:], fp16x2, once per block ----
    uint32_t af[2][8][4];
    #pragma unroll
    for (int mt = 0; mt < 2; mt++) {
        const int ra = m0 + mt * 16 + g;
        #pragma unroll
        for (int kt = 0; kt < 8; kt++) {
            const int k0 = kt * 16 + 2 * q;
            af[mt][kt][0] = h2u(
                __floats2half2_rn(W2[k0 * H2 + ra], W2[(k0 + 1) * H2 + ra]));
            af[mt][kt][1] = h2u(
                __floats2half2_rn(W2[k0 * H2 + ra + 8], W2[(k0 + 1) * H2 + ra + 8]));
            af[mt][kt][2] = h2u(
                __floats2half2_rn(W2[(k0 + 8) * H2 + ra], W2[(k0 + 9) * H2 + ra]));
            af[mt][kt][3] = h2u(
                __floats2half2_rn(W2[(k0 + 8) * H2 + ra + 8], W2[(k0 + 9) * H2 + ra + 8]));
        }
    }

    // epilogue per-thread constants
    float c2[2][2], w3[2][2];
    #pragma unroll
    for (int mt = 0; mt < 2; mt++) {
        const int ra = m0 + mt * 16 + g;
        c2[mt][0] = b2[ra];     w3[mt][0] = W3[ra];
        c2[mt][1] = b2[ra + 8]; w3[mt][1] = W3[ra + 8];
    }
    const float b3 = b3p[0];

    const float* pvb = gv + b * NN * H1;
    const float* qlp = g_qlA + l * H1;

    for (int ii = 0; ii < 4; ii++) {
        const int i = i0 + ii;
        __syncthreads();   // s_h free; s_part consumed

        // ---- Phase A: s_h[j][kw] = half2(relu(u+pj)) ----
        {
            const float* gui = gu + (b * NN + i) * H1;
            #pragma unroll 4
            for (int t = tid; t < NN * 32; t += 256) {
                const int j  = t >> 5;
                const int k4 = (t & 31) * 4;
                float4 u4 = *(const float4*)(gui + k4);
                if (!intra) {
                    const float4 q4 = *(const float4*)(qlp + k4);
                    u4.x += q4.x; u4.y += q4.y; u4.z += q4.z; u4.w += q4.w;
                }
                const float4 p4 = *(const float4*)(pvb + j * H1 + k4);
                const __half2 h01 = __floats2half2_rn(fmaxf(u4.x + p4.x, 0.f),
                                                      fmaxf(u4.y + p4.y, 0.f));
                const __half2 h23 = __floats2half2_rn(fmaxf(u4.z + p4.z, 0.f),
                                                      fmaxf(u4.w + p4.w, 0.f));
                uint2 pk;
                pk.x = h2u(h01);
                pk.y = h2u(h23);
                *(uint2*)(s_h + j * ST + (t & 31) * 2) = pk;
            }
        }
        __syncthreads();

        // ---- MMA + fused epilogue per n-tile ----
        #pragma unroll 1
        for (int nt = 0; nt < 5; nt++) {
            const int n0 = jg * 40 + nt * 8;
            const uint32_t* hrow = s_h + (n0 + g) * ST + q;

            float d[2][4];
            #pragma unroll
            for (int mt = 0; mt < 2; mt++)
                d[mt][0] = d[mt][1] = d[mt][2] = d[mt][3] = 0.f;

            #pragma unroll
            for (int kt = 0; kt < 8; kt++) {
                const uint32_t b0v = hrow[kt * 8];
                const uint32_t b1v = hrow[kt * 8 + 4];
                mma_f16(d[0][0], d[0][1], d[0][2], d[0][3],
                        af[0][kt][0], af[0][kt][1], af[0][kt][2], af[0][kt][3],
                        b0v, b1v);
                mma_f16(d[1][0], d[1][1], d[1][2], d[1][3],
                        af[1][kt][0], af[1][kt][1], af[1][kt][2], af[1][kt][3],
                        b0v, b1v);
            }

            // relu(d + b2)*W3, fold 4 m-rows held by this thread
            float p0 = 0.f, p1 = 0.f;
            #pragma unroll
            for (int mt = 0; mt < 2; mt++) {
                p0 += fmaxf(d[mt][0] + c2[mt][0], 0.f) * w3[mt][0]
                    + fmaxf(d[mt][2] + c2[mt][1], 0.f) * w3[mt][1];
                p1 += fmaxf(d[mt][1] + c2[mt][0], 0.f) * w3[mt][0]
                    + fmaxf(d[mt][3] + c2[mt][1], 0.f) * w3[mt][1];
            }
            // reduce over g (lanes stride 4)
            p0 += __shfl_xor_sync(0xFFFFFFFFu, p0, 4);
            p0 += __shfl_xor_sync(0xFFFFFFFFu, p0, 8);
            p0 += __shfl_xor_sync(0xFFFFFFFFu, p0, 16);
            p1 += __shfl_xor_sync(0xFFFFFFFFu, p1, 4);
            p1 += __shfl_xor_sync(0xFFFFFFFFu, p1, 8);
            p1 += __shfl_xor_sync(0xFFFFFFFFu, p1, 16);
            if (g == 0) {
                s_part[mg * NN + n0 + 2 * q]     = p0;
                s_part[mg * NN + n0 + 2 * q + 1] = p1;
            }
        }
        __syncthreads();

        // ---- final: sum 2 mg partials, sigmoid, mask, store ----
        if (tid < NN) {
            const int j = tid;
            const float lg = b3 + s_part[j] + s_part[NN + j];
            float sig = 1.f / (1.f + __expf(-lg));
            if (i == j) sig = 0.f;
            size_t off;
            if (intra)
                off = ((size_t)(b * NN + i)) * NN + j;
            else
                off = (size_t)BB * NN * NN +
                      ((size_t)((b * LL + l) * NN) + i) * NN + j;
            out[off] = sig;
        }
    }
}

static const int PAIR_SMEM_BYTES =
    (NN * ST) * (int)sizeof(uint32_t) + 2 * NN * (int)sizeof(float);

extern "C" void kernel_launch(void* const* d_in, const int* in_sizes, int n_in,
                              void* d_out, int out_size)
{
    const float* ne  = (const float*)d_in[0];
    const float* zi  = (const float*)d_in[1];
    const float* ze  = (const float*)d_in[2];
    const float* lag = (const float*)d_in[3];
    const float* Wi1 = (const float*)d_in[4];
    const float* bi1 = (const float*)d_in[5];
    const float* Wi2 = (const float*)d_in[6];
    const float* bi2 = (const float*)d_in[7];
    const float* Wi3 = (const float*)d_in[8];
    const float* bi3 = (const float*)d_in[9];
    const float* Wl1 = (const float*)d_in[10];
    const float* bl1 = (const float*)d_in[11];
    const float* Wl2 = (const float*)d_in[12];
    const float* bl2 = (const float*)d_in[13];
    const float* Wl3 = (const float*)d_in[14];
    const float* bl3 = (const float*)d_in[15];
    float* out = (float*)d_out;

    cudaFuncSetAttribute(pair_mma_kernel,
                         cudaFuncAttributeMaxDynamicSharedMemorySize,
                         PAIR_SMEM_BYTES);

    proj_kernel<<<BB * NN, H1>>>(ne, zi, ze, lag, Wi1, bi1, Wl1, bl1);

    const int nblocks = BB * (NN / 4) + BB * LL * (NN / 4);  // 800
    pair_mma_kernel<<<nblocks, 256, PAIR_SMEM_BYTES>>>(
        Wi2, bi2, Wi3, bi3, Wl2, bl2, Wl3, bl3, out);
}

// round 12
// speedup vs baseline: 5.3361x; 1.0590x over previous
#include <cuda_runtime.h>
#include <cuda_fp16.h>
#include <cstdint>

#define BB 4
#define NN 160
#define DD 64
#define ZIc 64
#define ZEc 64
#define LL 4
#define LEc 8
#define H1 128
#define H2 64
#define ST 68   // s_h row stride in 32-bit words (64 data + 4 pad; ST%32==4)

// ---------------- device scratch (allocation-free) ----------------
__device__ float g_piA[BB * NN * H1];
__device__ float g_pjA[BB * NN * H1];
__device__ float g_qiA[BB * NN * H1];
__device__ float g_qjA[BB * NN * H1];
__device__ float g_qlA[LL * H1];

__device__ __forceinline__ uint32_t h2u(__half2 h) {
    return *reinterpret_cast<uint32_t*>(&h);
}

__device__ __forceinline__ void mma_f16(float& d0, float& d1, float& d2, float& d3,
                                        uint32_t a0, uint32_t a1, uint32_t a2, uint32_t a3,
                                        uint32_t b0, uint32_t b1) {
    asm volatile(
        "mma.sync.aligned.m16n8k16.row.col.f32.f16.f16.f32 "
        "{%0,%1,%2,%3}, {%4,%5,%6,%7}, {%8,%9}, {%0,%1,%2,%3};"
        : "+f"(d0), "+f"(d1), "+f"(d2), "+f"(d3)
        : "r"(a0), "r"(a1), "r"(a2), "r"(a3), "r"(b0), "r"(b1));
}

// ---------------------------------------------------------------------------
// Kernel 1: per-(b,n) projections (tiny)
// ---------------------------------------------------------------------------
__global__ void proj_kernel(const float* __restrict__ ne,
                            const float* __restrict__ zi,
                            const float* __restrict__ ze,
                            const float* __restrict__ lag,
                            const float* __restrict__ Wi1,
                            const float* __restrict__ bi1,
                            const float* __restrict__ Wl1,
                            const float* __restrict__ bl1)
{
    __shared__ float s_ne[DD], s_zi[ZIc], s_ze[ZEc];
    const int bid = blockIdx.x;
    const int b   = bid / NN;
    const int k   = threadIdx.x;

    if (k < DD)  s_ne[k] = ne[bid * DD + k];
    if (k < ZIc) s_zi[k] = zi[b * ZIc + k];
    if (k < ZEc) s_ze[k] = ze[b * ZEc + k];
    __syncthreads();

    float api = bi1[k];
    float apj = 0.f;
    float aqi = bl1[k];
    float aqj = 0.f;

    #pragma unroll 8
    for (int d = 0; d < DD; d++) {
        const float nd = s_ne[d];
        api += nd * Wi1[d * H1 + k];
        apj += nd * Wi1[(DD + d) * H1 + k];
        aqi += nd * Wl1[d * H1 + k];
        aqj += nd * Wl1[(DD + d) * H1 + k];
    }
    #pragma unroll 8
    for (int z = 0; z < ZIc; z++) {
        api += s_zi[z] * Wi1[(2 * DD + z) * H1 + k];
        aqi += s_ze[z] * Wl1[(2 * DD + z) * H1 + k];
    }

    g_piA[bid * H1 + k] = api;
    g_pjA[bid * H1 + k] = apj;
    g_qiA[bid * H1 + k] = aqi;
    g_qjA[bid * H1 + k] = aqj;

    if (bid == 0) {
        #pragma unroll
        for (int l = 0; l < LL; l++) {
            float a = 0.f;
            #pragma unroll
            for (int e = 0; e < LEc; e++)
                a += lag[l * LEc + e] * Wl1[(2 * DD + ZEc + e) * H1 + k];
            g_qlA[l * H1 + k] = a;
        }
    }
}

// ---------------------------------------------------------------------------
// Kernel 2: pairwise MLP via mma.sync fp16 m16n8k16, 2 i's per phase.
// Block = one (b,[l]) x 4 i's (2 pairs), 256 thr = 8 warps.
//   warp: mg = wid&1 (m-half), jg = wid>>1 (40 j per i2 -> 10 n-tiles/pair).
// A = W2^T fp16 fragments in regs (64 regs), loaded once per block.
// B = h for BOTH i's of the pair: 320 rows x ST words smem.
// Barriers: 2 per pair (4 per block). s_part double-buffered.
// ---------------------------------------------------------------------------
extern __shared__ uint32_t smemw[];

__global__ __launch_bounds__(256, 2) void pair_mma_kernel(
    const float* __restrict__ Wi2, const float* __restrict__ bi2,
    const float* __restrict__ Wi3, const float* __restrict__ bi3,
    const float* __restrict__ Wl2, const float* __restrict__ bl2,
    const float* __restrict__ Wl3, const float* __restrict__ bl3,
    float* __restrict__ out)
{
    uint32_t* s_h    = smemw;                          // 320 * ST words
    float*    s_part = (float*)(smemw + 2 * NN * ST);  // [2 buf][2 mg][320]

    const int tid  = threadIdx.x;
    const int wid  = tid >> 5;
    const int lane = tid & 31;
    const int bid  = blockIdx.x;

    const bool intra = (bid < BB * (NN / 4));
    int b, l = 0, i0;
    const float *gu, *gv, *W2, *b2, *W3, *b3p;
    if (intra) {
        b  = bid / (NN / 4);
        i0 = (bid % (NN / 4)) * 4;
        gu = g_piA; gv = g_pjA; W2 = Wi2; b2 = bi2; W3 = Wi3; b3p = bi3;
    } else {
        const int e = bid - BB * (NN / 4);
        b = e / (LL * (NN / 4));
        const int r = e % (LL * (NN / 4));
        l  = r / (NN / 4);
        i0 = (r % (NN / 4)) * 4;
        gu = g_qiA; gv = g_qjA; W2 = Wl2; b2 = bl2; W3 = Wl3; b3p = bl3;
    }

    const int g  = lane >> 2;     // 0..7
    const int q  = lane & 3;      // 0..3
    const int mg = wid & 1;       // m-half
    const int jg = wid >> 1;      // 0..3
    const int m0 = mg * 32;

    // ---- A fragments: W2T[m0..m0+31][:], fp16x2, once per block ----
    uint32_t af[2][8][4];
    #pragma unroll
    for (int mt = 0; mt < 2; mt++) {
        const int ra = m0 + mt * 16 + g;
        #pragma unroll
        for (int kt = 0; kt < 8; kt++) {
            const int k0 = kt * 16 + 2 * q;
            af[mt][kt][0] = h2u(
                __floats2half2_rn(W2[k0 * H2 + ra], W2[(k0 + 1) * H2 + ra]));
            af[mt][kt][1] = h2u(
                __floats2half2_rn(W2[k0 * H2 + ra + 8], W2[(k0 + 1) * H2 + ra + 8]));
            af[mt][kt][2] = h2u(
                __floats2half2_rn(W2[(k0 + 8) * H2 + ra], W2[(k0 + 9) * H2 + ra]));
            af[mt][kt][3] = h2u(
                __floats2half2_rn(W2[(k0 + 8) * H2 + ra + 8], W2[(k0 + 9) * H2 + ra + 8]));
        }
    }

    // epilogue per-thread constants
    float c2[2][2], w3[2][2];
    #pragma unroll
    for (int mt = 0; mt < 2; mt++) {
        const int ra = m0 + mt * 16 + g;
        c2[mt][0] = b2[ra];     w3[mt][0] = W3[ra];
        c2[mt][1] = b2[ra + 8]; w3[mt][1] = W3[ra + 8];
    }
    const float b3 = b3p[0];

    const float* pvb = gv + b * NN * H1;
    const float* qlp = g_qlA + l * H1;

    #pragma unroll 1
    for (int pr = 0; pr < 2; pr++) {
        const int ibase = i0 + pr * 2;
        float* part = s_part + pr * 2 * 2 * NN;   // this pair's buffer

        // ---- Phase A: s_h[(i2*NN+j)][kw] = half2(relu(u+pj)), i2=0,1 ----
        #pragma unroll
        for (int i2 = 0; i2 < 2; i2++) {
            const float* gui = gu + (b * NN + ibase + i2) * H1;
            uint32_t* shp = s_h + i2 * NN * ST;
            #pragma unroll 4
            for (int t = tid; t < NN * 32; t += 256) {
                const int j  = t >> 5;
                const int k4 = (t & 31) * 4;
                float4 u4 = *(const float4*)(gui + k4);
                if (!intra) {
                    const float4 q4 = *(const float4*)(qlp + k4);
                    u4.x += q4.x; u4.y += q4.y; u4.z += q4.z; u4.w += q4.w;
                }
                const float4 p4 = *(const float4*)(pvb + j * H1 + k4);
                const __half2 h01 = __floats2half2_rn(fmaxf(u4.x + p4.x, 0.f),
                                                      fmaxf(u4.y + p4.y, 0.f));
                const __half2 h23 = __floats2half2_rn(fmaxf(u4.z + p4.z, 0.f),
                                                      fmaxf(u4.w + p4.w, 0.f));
                uint2 pk;
                pk.x = h2u(h01);
                pk.y = h2u(h23);
                *(uint2*)(shp + j * ST + (t & 31) * 2) = pk;
            }
        }
        __syncthreads();

        // ---- MMA + fused epilogue: 10 n-tiles (2 i2 x 5) ----
        #pragma unroll 1
        for (int i2 = 0; i2 < 2; i2++) {
            #pragma unroll 1
            for (int nt = 0; nt < 5; nt++) {
                const int n0 = jg * 40 + nt * 8;
                const uint32_t* hrow = s_h + (i2 * NN + n0 + g) * ST + q;

                float d[2][4];
                #pragma unroll
                for (int mt = 0; mt < 2; mt++)
                    d[mt][0] = d[mt][1] = d[mt][2] = d[mt][3] = 0.f;

                #pragma unroll
                for (int kt = 0; kt < 8; kt++) {
                    const uint32_t b0v = hrow[kt * 8];
                    const uint32_t b1v = hrow[kt * 8 + 4];
                    mma_f16(d[0][0], d[0][1], d[0][2], d[0][3],
                            af[0][kt][0], af[0][kt][1], af[0][kt][2], af[0][kt][3],
                            b0v, b1v);
                    mma_f16(d[1][0], d[1][1], d[1][2], d[1][3],
                            af[1][kt][0], af[1][kt][1], af[1][kt][2], af[1][kt][3],
                            b0v, b1v);
                }

                float p0 = 0.f, p1 = 0.f;
                #pragma unroll
                for (int mt = 0; mt < 2; mt++) {
                    p0 += fmaxf(d[mt][0] + c2[mt][0], 0.f) * w3[mt][0]
                        + fmaxf(d[mt][2] + c2[mt][1], 0.f) * w3[mt][1];
                    p1 += fmaxf(d[mt][1] + c2[mt][0], 0.f) * w3[mt][0]
                        + fmaxf(d[mt][3] + c2[mt][1], 0.f) * w3[mt][1];
                }
                p0 += __shfl_xor_sync(0xFFFFFFFFu, p0, 4);
                p0 += __shfl_xor_sync(0xFFFFFFFFu, p0, 8);
                p0 += __shfl_xor_sync(0xFFFFFFFFu, p0, 16);
                p1 += __shfl_xor_sync(0xFFFFFFFFu, p1, 4);
                p1 += __shfl_xor_sync(0xFFFFFFFFu, p1, 8);
                p1 += __shfl_xor_sync(0xFFFFFFFFu, p1, 16);
                if (g == 0) {
                    part[(mg * 2 + i2) * NN + n0 + 2 * q]     = p0;
                    part[(mg * 2 + i2) * NN + n0 + 2 * q + 1] = p1;
                }
            }
        }
        __syncthreads();

        // ---- final: sum 2 mg partials, sigmoid, mask, store ----
        // c in [0, 320): i2 = c/160, j = c%160
        for (int c = tid; c < 2 * NN; c += 256) {
            const int i2 = (c >= NN) ? 1 : 0;
            const int j  = c - i2 * NN;
            const int i  = ibase + i2;
            const float lg = b3 + part[i2 * NN + j] + part[(2 + i2) * NN + j];
            float sig = 1.f / (1.f + __expf(-lg));
            if (i == j) sig = 0.f;
            size_t off;
            if (intra)
                off = ((size_t)(b * NN + i)) * NN + j;
            else
                off = (size_t)BB * NN * NN +
                      ((size_t)((b * LL + l) * NN) + i) * NN + j;
            out[off] = sig;
        }
        // no sync: next Phase A writes s_h, already fenced by the MMA-exit
        // sync above; this pair's part buffer is never rewritten.
    }
}

static const int PAIR_SMEM_BYTES =
    (2 * NN * ST) * (int)sizeof(uint32_t) + 2 * 2 * 2 * NN * (int)sizeof(float);

extern "C" void kernel_launch(void* const* d_in, const int* in_sizes, int n_in,
                              void* d_out, int out_size)
{
    const float* ne  = (const float*)d_in[0];
    const float* zi  = (const float*)d_in[1];
    const float* ze  = (const float*)d_in[2];
    const float* lag = (const float*)d_in[3];
    const float* Wi1 = (const float*)d_in[4];
    const float* bi1 = (const float*)d_in[5];
    const float* Wi2 = (const float*)d_in[6];
    const float* bi2 = (const float*)d_in[7];
    const float* Wi3 = (const float*)d_in[8];
    const float* bi3 = (const float*)d_in[9];
    const float* Wl1 = (const float*)d_in[10];
    const float* bl1 = (const float*)d_in[11];
    const float* Wl2 = (const float*)d_in[12];
    const float* bl2 = (const float*)d_in[13];
    const float* Wl3 = (const float*)d_in[14];
    const float* bl3 = (const float*)d_in[15];
    float* out = (float*)d_out;

    cudaFuncSetAttribute(pair_mma_kernel,
                         cudaFuncAttributeMaxDynamicSharedMemorySize,
                         PAIR_SMEM_BYTES);

    proj_kernel<<<BB * NN, H1>>>(ne, zi, ze, lag, Wi1, bi1, Wl1, bl1);

    const int nblocks = BB * (NN / 4) + BB * LL * (NN / 4);  // 800
    pair_mma_kernel<<<nblocks, 256, PAIR_SMEM_BYTES>>>(
        Wi2, bi2, Wi3, bi3, Wl2, bl2, Wl3, bl3, out);
}

// round 13
// speedup vs baseline: 6.1298x; 1.1487x over previous
#include <cuda_runtime.h>
#include <cuda_fp16.h>
#include <cstdint>

#define BB 4
#define NN 160
#define DD 64
#define ZIc 64
#define ZEc 64
#define LL 4
#define LEc 8
#define H1 128
#define H2 64
#define ST 68   // row stride in 32-bit words for s_pj2 / s_h (64 data + 4 pad)

// ---------------- device scratch (allocation-free) ----------------
__device__ float g_piA[BB * NN * H1];
__device__ float g_pjA[BB * NN * H1];
__device__ float g_qiA[BB * NN * H1];
__device__ float g_qjA[BB * NN * H1];
__device__ float g_qlA[LL * H1];

__device__ __forceinline__ uint32_t h2u(__half2 h) {
    return *reinterpret_cast<uint32_t*>(&h);
}
__device__ __forceinline__ __half2 u2h(uint32_t u) {
    return *reinterpret_cast<__half2*>(&u);
}

__device__ __forceinline__ void mma_f16(float& d0, float& d1, float& d2, float& d3,
                                        uint32_t a0, uint32_t a1, uint32_t a2, uint32_t a3,
                                        uint32_t b0, uint32_t b1) {
    asm volatile(
        "mma.sync.aligned.m16n8k16.row.col.f32.f16.f16.f32 "
        "{%0,%1,%2,%3}, {%4,%5,%6,%7}, {%8,%9}, {%0,%1,%2,%3};"
        : "+f"(d0), "+f"(d1), "+f"(d2), "+f"(d3)
        : "r"(a0), "r"(a1), "r"(a2), "r"(a3), "r"(b0), "r"(b1));
}

__device__ __forceinline__ void ldmx4(uint32_t& r0, uint32_t& r1,
                                      uint32_t& r2, uint32_t& r3, uint32_t addr) {
    asm volatile(
        "ldmatrix.sync.aligned.m8n8.x4.shared.b16 {%0,%1,%2,%3}, [%4];"
        : "=r"(r0), "=r"(r1), "=r"(r2), "=r"(r3) : "r"(addr));
}

// ---------------------------------------------------------------------------
// Kernel 1: per-(b,n) projections (tiny)
// ---------------------------------------------------------------------------
__global__ void proj_kernel(const float* __restrict__ ne,
                            const float* __restrict__ zi,
                            const float* __restrict__ ze,
                            const float* __restrict__ lag,
                            const float* __restrict__ Wi1,
                            const float* __restrict__ bi1,
                            const float* __restrict__ Wl1,
                            const float* __restrict__ bl1)
{
    __shared__ float s_ne[DD], s_zi[ZIc], s_ze[ZEc];
    const int bid = blockIdx.x;
    const int b   = bid / NN;
    const int k   = threadIdx.x;

    if (k < DD)  s_ne[k] = ne[bid * DD + k];
    if (k < ZIc) s_zi[k] = zi[b * ZIc + k];
    if (k < ZEc) s_ze[k] = ze[b * ZEc + k];
    __syncthreads();

    float api = bi1[k];
    float apj = 0.f;
    float aqi = bl1[k];
    float aqj = 0.f;

    #pragma unroll 8
    for (int d = 0; d < DD; d++) {
        const float nd = s_ne[d];
        api += nd * Wi1[d * H1 + k];
        apj += nd * Wi1[(DD + d) * H1 + k];
        aqi += nd * Wl1[d * H1 + k];
        aqj += nd * Wl1[(DD + d) * H1 + k];
    }
    #pragma unroll 8
    for (int z = 0; z < ZIc; z++) {
        api += s_zi[z] * Wi1[(2 * DD + z) * H1 + k];
        aqi += s_ze[z] * Wl1[(2 * DD + z) * H1 + k];
    }

    g_piA[bid * H1 + k] = api;
    g_pjA[bid * H1 + k] = apj;
    g_qiA[bid * H1 + k] = aqi;
    g_qjA[bid * H1 + k] = aqj;

    if (bid == 0) {
        #pragma unroll
        for (int l = 0; l < LL; l++) {
            float a = 0.f;
            #pragma unroll
            for (int e = 0; e < LEc; e++)
                a += lag[l * LEc + e] * Wl1[(2 * DD + ZEc + e) * H1 + k];
            g_qlA[l * H1 + k] = a;
        }
    }
}

// ---------------------------------------------------------------------------
// Kernel 2: fp16 mma.sync pairwise MLP with half2 Phase A + ldmatrix.
// Block = one (b,[l]) x 4 i's, 256 thr = 8 warps.
//   warp: mg = wid&1 (m-half), jg = wid>>1 (40 j -> 5 n-tiles).
// Per block: stage pj as half2 (s_pj2) once; A-frags (W2^T fp16) in regs once.
// Per i: u -> half2 (64 thr); Phase A: s_h = hmax2(hadd2(u2,pj2),0) (pure LDS);
//   MMA: per n-tile 4 ldmatrix.x4 + 16 HMMA + fused epilogue -> s_part;
//   final: sum 2 mg partials, sigmoid, mask, store.
// ---------------------------------------------------------------------------
extern __shared__ uint32_t smemw[];

__global__ __launch_bounds__(256, 2) void pair_mma_kernel(
    const float* __restrict__ Wi2, const float* __restrict__ bi2,
    const float* __restrict__ Wi3, const float* __restrict__ bi3,
    const float* __restrict__ Wl2, const float* __restrict__ bl2,
    const float* __restrict__ Wl3, const float* __restrict__ bl3,
    float* __restrict__ out)
{
    uint32_t* s_pj2  = smemw;                       // NN*ST words
    uint32_t* s_h    = smemw + NN * ST;             // NN*ST words
    uint32_t* s_u2   = smemw + 2 * NN * ST;         // 64 words
    float*    s_part = (float*)(smemw + 2 * NN * ST + 64);  // 2*NN floats

    const int tid  = threadIdx.x;
    const int wid  = tid >> 5;
    const int lane = tid & 31;
    const int bid  = blockIdx.x;

    const bool intra = (bid < BB * (NN / 4));
    int b, l = 0, i0;
    const float *gu, *gv, *W2, *b2, *W3, *b3p;
    if (intra) {
        b  = bid / (NN / 4);
        i0 = (bid % (NN / 4)) * 4;
        gu = g_piA; gv = g_pjA; W2 = Wi2; b2 = bi2; W3 = Wi3; b3p = bi3;
    } else {
        const int e = bid - BB * (NN / 4);
        b = e / (LL * (NN / 4));
        const int r = e % (LL * (NN / 4));
        l  = r / (NN / 4);
        i0 = (r % (NN / 4)) * 4;
        gu = g_qiA; gv = g_qjA; W2 = Wl2; b2 = bl2; W3 = Wl3; b3p = bl3;
    }

    const int g  = lane >> 2;     // 0..7
    const int q  = lane & 3;      // 0..3
    const int mg = wid & 1;       // m-half
    const int jg = wid >> 1;      // 0..3
    const int m0 = mg * 32;

    // ---- A fragments: W2T[m0..m0+31][:], fp16x2, once per block ----
    uint32_t af[2][8][4];
    #pragma unroll
    for (int mt = 0; mt < 2; mt++) {
        const int ra = m0 + mt * 16 + g;
        #pragma unroll
        for (int kt = 0; kt < 8; kt++) {
            const int k0 = kt * 16 + 2 * q;
            af[mt][kt][0] = h2u(
                __floats2half2_rn(W2[k0 * H2 + ra], W2[(k0 + 1) * H2 + ra]));
            af[mt][kt][1] = h2u(
                __floats2half2_rn(W2[k0 * H2 + ra + 8], W2[(k0 + 1) * H2 + ra + 8]));
            af[mt][kt][2] = h2u(
                __floats2half2_rn(W2[(k0 + 8) * H2 + ra], W2[(k0 + 9) * H2 + ra]));
            af[mt][kt][3] = h2u(
                __floats2half2_rn(W2[(k0 + 8) * H2 + ra + 8], W2[(k0 + 9) * H2 + ra + 8]));
        }
    }

    // epilogue per-thread constants
    float c2[2][2], w3[2][2];
    #pragma unroll
    for (int mt = 0; mt < 2; mt++) {
        const int ra = m0 + mt * 16 + g;
        c2[mt][0] = b2[ra];     w3[mt][0] = W3[ra];
        c2[mt][1] = b2[ra + 8]; w3[mt][1] = W3[ra + 8];
    }
    const float b3 = b3p[0];

    // ---- stage pj as half2 once per block ----
    {
        const float* pvb = gv + b * NN * H1;
        #pragma unroll 4
        for (int c = tid; c < NN * 32; c += 256) {
            const int j  = c >> 5;
            const int kq = c & 31;
            const float4 p4 = *(const float4*)(pvb + j * H1 + kq * 4);
            uint2 pk;
            pk.x = h2u(__floats2half2_rn(p4.x, p4.y));
            pk.y = h2u(__floats2half2_rn(p4.z, p4.w));
            *(uint2*)(s_pj2 + j * ST + kq * 2) = pk;
        }
    }

    const uint32_t sh_b = (uint32_t)__cvta_generic_to_shared(s_h);
    const float* qlp = g_qlA + l * H1;
    const __half2 hz = u2h(0u);

    __syncthreads();

    #pragma unroll 1
    for (int ii = 0; ii < 4; ii++) {
        const int i = i0 + ii;

        // ---- u -> half2 (64 threads) ----
        if (tid < 64) {
            const float* gui = gu + (b * NN + i) * H1 + 2 * tid;
            float f0 = gui[0], f1 = gui[1];
            if (!intra) { f0 += qlp[2 * tid]; f1 += qlp[2 * tid + 1]; }
            s_u2[tid] = h2u(__floats2half2_rn(f0, f1));
        }
        __syncthreads();

        // ---- Phase A: s_h = hmax2(hadd2(u2, pj2), 0) ----
        #pragma unroll
        for (int it = 0; it < 10; it++) {
            const int c  = it * 256 + tid;   // 0..2559 float4-chunks
            const int j  = c >> 4;
            const int kc = c & 15;
            const uint4 pv = *(const uint4*)(s_pj2 + j * ST + kc * 4);
            const uint4 uv = *(const uint4*)(s_u2 + kc * 4);
            uint4 hv;
            hv.x = h2u(__hmax2(__hadd2(u2h(uv.x), u2h(pv.x)), hz));
            hv.y = h2u(__hmax2(__hadd2(u2h(uv.y), u2h(pv.y)), hz));
            hv.z = h2u(__hmax2(__hadd2(u2h(uv.z), u2h(pv.z)), hz));
            hv.w = h2u(__hmax2(__hadd2(u2h(uv.w), u2h(pv.w)), hz));
            *(uint4*)(s_h + j * ST + kc * 4) = hv;
        }
        __syncthreads();

        // ---- MMA + fused epilogue per n-tile ----
        #pragma unroll 1
        for (int nt = 0; nt < 5; nt++) {
            const int n0 = jg * 40 + nt * 8;
            // ldmatrix lane address: matrix mi = lane>>3, row = n0+(lane&7)
            const uint32_t mi = (uint32_t)(lane >> 3);
            const uint32_t la = sh_b +
                (((uint32_t)(n0 + (lane & 7)) * ST) +
                 (mi & 1) * 4 + (mi >> 1) * 8) * 4;

            float d[2][4];
            #pragma unroll
            for (int mt = 0; mt < 2; mt++)
                d[mt][0] = d[mt][1] = d[mt][2] = d[mt][3] = 0.f;

            #pragma unroll
            for (int p = 0; p < 4; p++) {
                uint32_t r0, r1, r2, r3;
                ldmx4(r0, r1, r2, r3, la + p * 64);
                const int kt = 2 * p;
                mma_f16(d[0][0], d[0][1], d[0][2], d[0][3],
                        af[0][kt][0], af[0][kt][1], af[0][kt][2], af[0][kt][3],
                        r0, r1);
                mma_f16(d[1][0], d[1][1], d[1][2], d[1][3],
                        af[1][kt][0], af[1][kt][1], af[1][kt][2], af[1][kt][3],
                        r0, r1);
                mma_f16(d[0][0], d[0][1], d[0][2], d[0][3],
                        af[0][kt + 1][0], af[0][kt + 1][1], af[0][kt + 1][2], af[0][kt + 1][3],
                        r2, r3);
                mma_f16(d[1][0], d[1][1], d[1][2], d[1][3],
                        af[1][kt + 1][0], af[1][kt + 1][1], af[1][kt + 1][2], af[1][kt + 1][3],
                        r2, r3);
            }

            // relu(d + b2)*W3, fold 4 m-rows held by this thread
            float p0 = 0.f, p1 = 0.f;
            #pragma unroll
            for (int mt = 0; mt < 2; mt++) {
                p0 += fmaxf(d[mt][0] + c2[mt][0], 0.f) * w3[mt][0]
                    + fmaxf(d[mt][2] + c2[mt][1], 0.f) * w3[mt][1];
                p1 += fmaxf(d[mt][1] + c2[mt][0], 0.f) * w3[mt][0]
                    + fmaxf(d[mt][3] + c2[mt][1], 0.f) * w3[mt][1];
            }
            p0 += __shfl_xor_sync(0xFFFFFFFFu, p0, 4);
            p0 += __shfl_xor_sync(0xFFFFFFFFu, p0, 8);
            p0 += __shfl_xor_sync(0xFFFFFFFFu, p0, 16);
            p1 += __shfl_xor_sync(0xFFFFFFFFu, p1, 4);
            p1 += __shfl_xor_sync(0xFFFFFFFFu, p1, 8);
            p1 += __shfl_xor_sync(0xFFFFFFFFu, p1, 16);
            if (g == 0) {
                s_part[mg * NN + n0 + 2 * q]     = p0;
                s_part[mg * NN + n0 + 2 * q + 1] = p1;
            }
        }
        __syncthreads();

        // ---- final: sum 2 mg partials, sigmoid, mask, store ----
        if (tid < NN) {
            const int j = tid;
            const float lg = b3 + s_part[j] + s_part[NN + j];
            float sig = 1.f / (1.f + __expf(-lg));
            if (i == j) sig = 0.f;
            size_t off;
            if (intra)
                off = ((size_t)(b * NN + i)) * NN + j;
            else
                off = (size_t)BB * NN * NN +
                      ((size_t)((b * LL + l) * NN) + i) * NN + j;
            out[off] = sig;
        }
        // next iteration's first __syncthreads (after u2 staging) orders
        // s_part rewrite after these reads.
    }
}

static const int PAIR_SMEM_BYTES =
    (2 * NN * ST + 64) * (int)sizeof(uint32_t) + 2 * NN * (int)sizeof(float);

extern "C" void kernel_launch(void* const* d_in, const int* in_sizes, int n_in,
                              void* d_out, int out_size)
{
    const float* ne  = (const float*)d_in[0];
    const float* zi  = (const float*)d_in[1];
    const float* ze  = (const float*)d_in[2];
    const float* lag = (const float*)d_in[3];
    const float* Wi1 = (const float*)d_in[4];
    const float* bi1 = (const float*)d_in[5];
    const float* Wi2 = (const float*)d_in[6];
    const float* bi2 = (const float*)d_in[7];
    const float* Wi3 = (const float*)d_in[8];
    const float* bi3 = (const float*)d_in[9];
    const float* Wl1 = (const float*)d_in[10];
    const float* bl1 = (const float*)d_in[11];
    const float* Wl2 = (const float*)d_in[12];
    const float* bl2 = (const float*)d_in[13];
    const float* Wl3 = (const float*)d_in[14];
    const float* bl3 = (const float*)d_in[15];
    float* out = (float*)d_out;

    cudaFuncSetAttribute(pair_mma_kernel,
                         cudaFuncAttributeMaxDynamicSharedMemorySize,
                         PAIR_SMEM_BYTES);

    proj_kernel<<<BB * NN, H1>>>(ne, zi, ze, lag, Wi1, bi1, Wl1, bl1);

    const int nblocks = BB * (NN / 4) + BB * LL * (NN / 4);  // 800
    pair_mma_kernel<<<nblocks, 256, PAIR_SMEM_BYTES>>>(
        Wi2, bi2, Wi3, bi3, Wl2, bl2, Wl3, bl3, out);
}

// round 14
// speedup vs baseline: 6.5862x; 1.0744x over previous
#include <cuda_runtime.h>
#include <cuda_fp16.h>
#include <cstdint>

#define BB 4
#define NN 160
#define DD 64
#define ZIc 64
#define ZEc 64
#define LL 4
#define LEc 8
#define H1 128
#define H2 64
#define ST 68   // s_h row stride in 32-bit words (64 data + 4 pad)

// ---------------- device scratch (allocation-free) ----------------
// half2-packed (uint32) precomputed operands
__device__ uint32_t g_u2i[BB * NN * 64];            // intra u  = pi + bi1
__device__ uint32_t g_pj2i[BB * NN * 64];           // intra pj
__device__ uint32_t g_pj2l[BB * NN * 64];           // inter pj (qj)
__device__ uint32_t g_u2l[BB * LL * NN * 64];       // inter u  = qi + ql + bl1

__device__ __forceinline__ uint32_t h2u(__half2 h) {
    return *reinterpret_cast<uint32_t*>(&h);
}
__device__ __forceinline__ __half2 u2h(uint32_t u) {
    return *reinterpret_cast<__half2*>(&u);
}

__device__ __forceinline__ void mma_f16(float& d0, float& d1, float& d2, float& d3,
                                        uint32_t a0, uint32_t a1, uint32_t a2, uint32_t a3,
                                        uint32_t b0, uint32_t b1) {
    asm volatile(
        "mma.sync.aligned.m16n8k16.row.col.f32.f16.f16.f32 "
        "{%0,%1,%2,%3}, {%4,%5,%6,%7}, {%8,%9}, {%0,%1,%2,%3};"
        : "+f"(d0), "+f"(d1), "+f"(d2), "+f"(d3)
        : "r"(a0), "r"(a1), "r"(a2), "r"(a3), "r"(b0), "r"(b1));
}

__device__ __forceinline__ void ldmx4(uint32_t& r0, uint32_t& r1,
                                      uint32_t& r2, uint32_t& r3, uint32_t addr) {
    asm volatile(
        "ldmatrix.sync.aligned.m8n8.x4.shared.b16 {%0,%1,%2,%3}, [%4];"
        : "=r"(r0), "=r"(r1), "=r"(r2), "=r"(r3) : "r"(addr));
}

// ---------------------------------------------------------------------------
// Kernel 1: projections + half2 packing. Block = (b,n), 128 threads (k).
// Emits u2i, pj2i, pj2l, u2l[l] as half2 words.
// ---------------------------------------------------------------------------
__global__ void proj_kernel(const float* __restrict__ ne,
                            const float* __restrict__ zi,
                            const float* __restrict__ ze,
                            const float* __restrict__ lag,
                            const float* __restrict__ Wi1,
                            const float* __restrict__ bi1,
                            const float* __restrict__ Wl1,
                            const float* __restrict__ bl1)
{
    __shared__ float s_ne[DD], s_zi[ZIc], s_ze[ZEc];
    __shared__ float s_pack[7][H1];
    const int bid = blockIdx.x;      // b*NN + n
    const int b   = bid / NN;
    const int n   = bid - b * NN;
    const int k   = threadIdx.x;

    if (k < DD)  s_ne[k] = ne[bid * DD + k];
    if (k < ZIc) s_zi[k] = zi[b * ZIc + k];
    if (k < ZEc) s_ze[k] = ze[b * ZEc + k];
    __syncthreads();

    float api = bi1[k];
    float apj = 0.f;
    float aqi = bl1[k];
    float aqj = 0.f;

    #pragma unroll 8
    for (int d = 0; d < DD; d++) {
        const float nd = s_ne[d];
        api += nd * Wi1[d * H1 + k];
        apj += nd * Wi1[(DD + d) * H1 + k];
        aqi += nd * Wl1[d * H1 + k];
        aqj += nd * Wl1[(DD + d) * H1 + k];
    }
    #pragma unroll 8
    for (int z = 0; z < ZIc; z++) {
        api += s_zi[z] * Wi1[(2 * DD + z) * H1 + k];
        aqi += s_ze[z] * Wl1[(2 * DD + z) * H1 + k];
    }

    // ql[l][k] inline (8-term dot each)
    float ql[LL];
    #pragma unroll
    for (int l = 0; l < LL; l++) {
        float a = 0.f;
        #pragma unroll
        for (int e = 0; e < LEc; e++)
            a += lag[l * LEc + e] * Wl1[(2 * DD + ZEc + e) * H1 + k];
        ql[l] = a;
    }

    s_pack[0][k] = api;
    s_pack[1][k] = apj;
    s_pack[2][k] = aqj;
    #pragma unroll
    for (int l = 0; l < LL; l++) s_pack[3 + l][k] = aqi + ql[l];
    __syncthreads();

    // pack 7*64 half2 words
    for (int idx = k; idx < 7 * 64; idx += H1) {
        const int row = idx >> 6;
        const int c   = idx & 63;
        const uint32_t v = h2u(__floats2half2_rn(s_pack[row][2 * c],
                                                 s_pack[row][2 * c + 1]));
        if (row == 0)      g_u2i[bid * 64 + c] = v;
        else if (row == 1) g_pj2i[bid * 64 + c] = v;
        else if (row == 2) g_pj2l[bid * 64 + c] = v;
        else {
            const int l = row - 3;
            g_u2l[((b * LL + l) * NN + n) * 64 + c] = v;
        }
    }
}

// ---------------------------------------------------------------------------
// Kernel 2: fp16 mma.sync pairwise MLP, pipelined double-buffered s_h.
// Block = one (b,[l]) x 4 i's, 256 thr = 8 warps.
//   warp: mg = wid&1 (m-half), jg = wid>>1 (40 j -> 5 n-tiles).
// Pipeline: A(0); sync; for i: { MMA(i) on buf[i&1] -> part[i];
//                                A(i+1) -> buf[(i+1)&1]; sync; store(i) }
// ---------------------------------------------------------------------------
extern __shared__ uint32_t smemw[];

__global__ __launch_bounds__(256, 2) void pair_mma_kernel(
    const float* __restrict__ Wi2, const float* __restrict__ bi2,
    const float* __restrict__ Wi3, const float* __restrict__ bi3,
    const float* __restrict__ Wl2, const float* __restrict__ bl2,
    const float* __restrict__ Wl3, const float* __restrict__ bl3,
    float* __restrict__ out)
{
    uint32_t* s_h0   = smemw;                       // NN*ST words
    uint32_t* s_h1   = smemw + NN * ST;             // NN*ST words
    float*    s_part = (float*)(smemw + 2 * NN * ST);  // [4][2][NN]

    const int tid  = threadIdx.x;
    const int wid  = tid >> 5;
    const int lane = tid & 31;
    const int bid  = blockIdx.x;

    const bool intra = (bid < BB * (NN / 4));
    int b, l = 0, i0;
    const float *W2, *b2, *W3, *b3p;
    const uint32_t *pj2, *u2base;
    if (intra) {
        b  = bid / (NN / 4);
        i0 = (bid % (NN / 4)) * 4;
        W2 = Wi2; b2 = bi2; W3 = Wi3; b3p = bi3;
        pj2 = g_pj2i + b * NN * 64;
        u2base = g_u2i + b * NN * 64;
    } else {
        const int e = bid - BB * (NN / 4);
        b = e / (LL * (NN / 4));
        const int r = e % (LL * (NN / 4));
        l  = r / (NN / 4);
        i0 = (r % (NN / 4)) * 4;
        W2 = Wl2; b2 = bl2; W3 = Wl3; b3p = bl3;
        pj2 = g_pj2l + b * NN * 64;
        u2base = g_u2l + (b * LL + l) * NN * 64;
    }

    const int g  = lane >> 2;     // 0..7
    const int q  = lane & 3;      // 0..3
    const int mg = wid & 1;       // m-half
    const int jg = wid >> 1;      // 0..3
    const int m0 = mg * 32;

    // ---- A fragments: W2T[m0..m0+31][:], fp16x2, once per block ----
    uint32_t af[2][8][4];
    #pragma unroll
    for (int mt = 0; mt < 2; mt++) {
        const int ra = m0 + mt * 16 + g;
        #pragma unroll
        for (int kt = 0; kt < 8; kt++) {
            const int k0 = kt * 16 + 2 * q;
            af[mt][kt][0] = h2u(
                __floats2half2_rn(W2[k0 * H2 + ra], W2[(k0 + 1) * H2 + ra]));
            af[mt][kt][1] = h2u(
                __floats2half2_rn(W2[k0 * H2 + ra + 8], W2[(k0 + 1) * H2 + ra + 8]));
            af[mt][kt][2] = h2u(
                __floats2half2_rn(W2[(k0 + 8) * H2 + ra], W2[(k0 + 9) * H2 + ra]));
            af[mt][kt][3] = h2u(
                __floats2half2_rn(W2[(k0 + 8) * H2 + ra + 8], W2[(k0 + 9) * H2 + ra + 8]));
        }
    }

    // epilogue per-thread constants
    float c2[2][2], w3[2][2];
    #pragma unroll
    for (int mt = 0; mt < 2; mt++) {
        const int ra = m0 + mt * 16 + g;
        c2[mt][0] = b2[ra];     w3[mt][0] = W3[ra];
        c2[mt][1] = b2[ra + 8]; w3[mt][1] = W3[ra + 8];
    }
    const float b3 = b3p[0];

    const __half2 hz = u2h(0u);
    const int kc = tid & 15;          // this thread's k-chunk (constant)
    const int jrow0 = tid >> 4;       // Phase A row base (j = it*16 + jrow0)

    // ---- Phase A lambda (i -> buffer) ----
    auto phaseA = [&](int i, uint32_t* sh) {
        const uint4 uv = *(const uint4*)(u2base + i * 64 + kc * 4);
        const uint32_t* pjr = pj2 + jrow0 * 64 + kc * 4;
        uint32_t* shw = sh + jrow0 * ST + kc * 4;
        #pragma unroll
        for (int it = 0; it < 10; it++) {
            const uint4 pv = *(const uint4*)(pjr + it * 16 * 64);
            uint4 hv;
            hv.x = h2u(__hmax2(__hadd2(u2h(uv.x), u2h(pv.x)), hz));
            hv.y = h2u(__hmax2(__hadd2(u2h(uv.y), u2h(pv.y)), hz));
            hv.z = h2u(__hmax2(__hadd2(u2h(uv.z), u2h(pv.z)), hz));
            hv.w = h2u(__hmax2(__hadd2(u2h(uv.w), u2h(pv.w)), hz));
            *(uint4*)(shw + it * 16 * ST) = hv;
        }
    };

    phaseA(i0, s_h0);
    __syncthreads();

    #pragma unroll 1
    for (int ii = 0; ii < 4; ii++) {
        const int i = i0 + ii;
        uint32_t* sh = (ii & 1) ? s_h1 : s_h0;
        float* part = s_part + ii * 2 * NN;

        // ---- MMA + fused epilogue per n-tile ----
        const uint32_t sh_b = (uint32_t)__cvta_generic_to_shared(sh);
        #pragma unroll 1
        for (int nt = 0; nt < 5; nt++) {
            const int n0 = jg * 40 + nt * 8;
            const uint32_t mi = (uint32_t)(lane >> 3);
            const uint32_t la = sh_b +
                (((uint32_t)(n0 + (lane & 7)) * ST) +
                 (mi & 1) * 4 + (mi >> 1) * 8) * 4;

            float d[2][4];
            #pragma unroll
            for (int mt = 0; mt < 2; mt++)
                d[mt][0] = d[mt][1] = d[mt][2] = d[mt][3] = 0.f;

            #pragma unroll
            for (int p = 0; p < 4; p++) {
                uint32_t r0, r1, r2, r3;
                ldmx4(r0, r1, r2, r3, la + p * 64);
                const int kt = 2 * p;
                mma_f16(d[0][0], d[0][1], d[0][2], d[0][3],
                        af[0][kt][0], af[0][kt][1], af[0][kt][2], af[0][kt][3],
                        r0, r1);
                mma_f16(d[1][0], d[1][1], d[1][2], d[1][3],
                        af[1][kt][0], af[1][kt][1], af[1][kt][2], af[1][kt][3],
                        r0, r1);
                mma_f16(d[0][0], d[0][1], d[0][2], d[0][3],
                        af[0][kt + 1][0], af[0][kt + 1][1], af[0][kt + 1][2], af[0][kt + 1][3],
                        r2, r3);
                mma_f16(d[1][0], d[1][1], d[1][2], d[1][3],
                        af[1][kt + 1][0], af[1][kt + 1][1], af[1][kt + 1][2], af[1][kt + 1][3],
                        r2, r3);
            }

            float p0 = 0.f, p1 = 0.f;
            #pragma unroll
            for (int mt = 0; mt < 2; mt++) {
                p0 += fmaxf(d[mt][0] + c2[mt][0], 0.f) * w3[mt][0]
                    + fmaxf(d[mt][2] + c2[mt][1], 0.f) * w3[mt][1];
                p1 += fmaxf(d[mt][1] + c2[mt][0], 0.f) * w3[mt][0]
                    + fmaxf(d[mt][3] + c2[mt][1], 0.f) * w3[mt][1];
            }
            p0 += __shfl_xor_sync(0xFFFFFFFFu, p0, 4);
            p0 += __shfl_xor_sync(0xFFFFFFFFu, p0, 8);
            p0 += __shfl_xor_sync(0xFFFFFFFFu, p0, 16);
            p1 += __shfl_xor_sync(0xFFFFFFFFu, p1, 4);
            p1 += __shfl_xor_sync(0xFFFFFFFFu, p1, 8);
            p1 += __shfl_xor_sync(0xFFFFFFFFu, p1, 16);
            if (g == 0) {
                part[mg * NN + n0 + 2 * q]     = p0;
                part[mg * NN + n0 + 2 * q + 1] = p1;
            }
        }

        // ---- Phase A for next i into the other buffer (overlaps MMA pipes) ----
        if (ii < 3) phaseA(i0 + ii + 1, (ii & 1) ? s_h0 : s_h1);
        __syncthreads();

        // ---- final: sum 2 mg partials, sigmoid, mask, store ----
        if (tid < NN) {
            const int j = tid;
            const float lg = b3 + part[j] + part[NN + j];
            float sig = 1.f / (1.f + __expf(-lg));
            if (i == j) sig = 0.f;
            size_t off;
            if (intra)
                off = ((size_t)(b * NN + i)) * NN + j;
            else
                off = (size_t)BB * NN * NN +
                      ((size_t)((b * LL + l) * NN) + i) * NN + j;
            out[off] = sig;
        }
    }
}

static const int PAIR_SMEM_BYTES =
    (2 * NN * ST) * (int)sizeof(uint32_t) + 4 * 2 * NN * (int)sizeof(float);

extern "C" void kernel_launch(void* const* d_in, const int* in_sizes, int n_in,
                              void* d_out, int out_size)
{
    const float* ne  = (const float*)d_in[0];
    const float* zi  = (const float*)d_in[1];
    const float* ze  = (const float*)d_in[2];
    const float* lag = (const float*)d_in[3];
    const float* Wi1 = (const float*)d_in[4];
    const float* bi1 = (const float*)d_in[5];
    const float* Wi2 = (const float*)d_in[6];
    const float* bi2 = (const float*)d_in[7];
    const float* Wi3 = (const float*)d_in[8];
    const float* bi3 = (const float*)d_in[9];
    const float* Wl1 = (const float*)d_in[10];
    const float* bl1 = (const float*)d_in[11];
    const float* Wl2 = (const float*)d_in[12];
    const float* bl2 = (const float*)d_in[13];
    const float* Wl3 = (const float*)d_in[14];
    const float* bl3 = (const float*)d_in[15];
    float* out = (float*)d_out;

    cudaFuncSetAttribute(pair_mma_kernel,
                         cudaFuncAttributeMaxDynamicSharedMemorySize,
                         PAIR_SMEM_BYTES);

    proj_kernel<<<BB * NN, H1>>>(ne, zi, ze, lag, Wi1, bi1, Wl1, bl1);

    const int nblocks = BB * (NN / 4) + BB * LL * (NN / 4);  // 800
    pair_mma_kernel<<<nblocks, 256, PAIR_SMEM_BYTES>>>(
        Wi2, bi2, Wi3, bi3, Wl2, bl2, Wl3, bl3, out);
}